// round 8
// baseline (speedup 1.0000x reference)
#include <cuda_runtime.h>
#include <math.h>
typedef unsigned long long ull;

constexpr int B=128,S=256,T=256,V=512,E=256,H=512,G=2048,H2=1024,EH2=1280;
constexpr int NB=128, NT=256;

__device__ __align__(256) float g_xs[(size_t)2*S*B*E];
__device__ __align__(256) float g_edec[(size_t)T*B*E];
__device__ __align__(256) float g_pre[(size_t)2*S*B*G];
__device__ __align__(256) float g_y0[(size_t)2*S*B*H2];
__device__ __align__(256) float g_enc[(size_t)S*B*H2];
__device__ __align__(256) float g_hb[2][2*B*H];
__device__ __align__(256) float g_cst[2*B*H];
__device__ __align__(256) float g_q[B*H2];
__device__ __align__(256) float g_ctx[B*H2];
__device__ __align__(256) float g_d0hb[2][B*H];
__device__ __align__(256) float g_d1hb[2][B*H];
__device__ __align__(256) float g_h0i[B*H];
__device__ __align__(256) float g_c0i[B*H];
__device__ __align__(256) float g_h1i[B*H];
__device__ __align__(256) float g_c1i[B*H];
// permuted weights (row g*H+j -> j*4+g) and permuted summed biases
__device__ __align__(256) float g_wE0ih[2*G*E];
__device__ __align__(256) float g_wE0hh[2*G*H];
__device__ __align__(256) float g_wE1ih[2*G*H2];
__device__ __align__(256) float g_wE1hh[2*G*H];
__device__ __align__(256) float g_wD0[G*EH2];
__device__ __align__(256) float g_wD0hh[G*H];
__device__ __align__(256) float g_wD1ih[G*H];
__device__ __align__(256) float g_wD1hh[G*H];
__device__ __align__(256) float g_be0[2*G];
__device__ __align__(256) float g_be1[2*G];
__device__ __align__(256) float g_bd0[G];
__device__ __align__(256) float g_bd1[G];

__device__ unsigned g_cnt, g_flag;

__device__ __forceinline__ void gbar(unsigned& phase)
{
    __syncthreads();
    if (threadIdx.x == 0) {
        __threadfence();
        const unsigned target = phase + 1;
        if (atomicAdd(&g_cnt, 1) == NB - 1) {
            g_cnt = 0; __threadfence();
            atomicExch(&g_flag, target);
        } else {
            while (*(volatile unsigned*)&g_flag < target) { __nanosleep(32); }
            __threadfence();
        }
        phase = target;
    }
    __syncthreads();
}

union UPair { ull u; float2 f; };
__device__ __forceinline__ ull dupf(float x){ ull r; asm("mov.b64 %0,{%1,%1};":"=l"(r):"f"(x)); return r; }
#define FMA2(d,a,b) asm("fma.rn.f32x2 %0,%1,%2,%0;":"+l"(d):"l"(a),"l"(b))
__device__ __forceinline__ float accf(ull a,int h){ UPair u; u.u=a; return h?u.f.y:u.f.x; }
__device__ __forceinline__ float sigf(float x){ return 1.f/(1.f+expf(-x)); }

// 64x64 tile core, K multiple of 16, register prefetch. A via __ldcg, W cached.
__device__ __forceinline__ void gcore2(const float* __restrict__ A,int lda,
    const float* __restrict__ W,int ldw,int K,
    float (*As)[66], ull (*Bs)[66], ull acc[2][4])
{
    const int tid=threadIdx.x, tx4=(tid&15)*4, ty4=(tid>>4)*4;
    const int lr=tid>>2, lk=(tid&3)*4;
    const float* ap=A+(size_t)lr*lda+lk;
    const float* wp=W+(size_t)lr*ldw+lk;
    float4 pa=__ldcg((const float4*)ap);
    float4 pw=*(const float4*)wp;
    #pragma unroll 1
    for(int kk=0;kk<K;kk+=16){
        As[lk+0][lr]=pa.x; As[lk+1][lr]=pa.y; As[lk+2][lr]=pa.z; As[lk+3][lr]=pa.w;
        Bs[lk+0][lr]=dupf(pw.x); Bs[lk+1][lr]=dupf(pw.y);
        Bs[lk+2][lr]=dupf(pw.z); Bs[lk+3][lr]=dupf(pw.w);
        __syncthreads();
        if(kk+16<K){ pa=__ldcg((const float4*)(ap+kk+16)); pw=*(const float4*)(wp+kk+16); }
        #pragma unroll
        for(int k=0;k<16;++k){
            const ull a01=*(const ull*)&As[k][ty4];
            const ull a23=*(const ull*)&As[k][ty4+2];
            const ulonglong2 b01=*(const ulonglong2*)&Bs[k][tx4];
            const ulonglong2 b23=*(const ulonglong2*)&Bs[k][tx4+2];
            FMA2(acc[0][0],a01,b01.x); FMA2(acc[0][1],a01,b01.y);
            FMA2(acc[0][2],a01,b23.x); FMA2(acc[0][3],a01,b23.y);
            FMA2(acc[1][0],a23,b01.x); FMA2(acc[1][1],a23,b01.y);
            FMA2(acc[1][2],a23,b23.x); FMA2(acc[1][3],a23,b23.y);
        }
        __syncthreads();
    }
}

// store with tile-relative bias (bias pre-offset by N-tile!)
__device__ __forceinline__ void store_out(ull acc[2][4], float* __restrict__ C,
                                          int ldc, const float* __restrict__ bias)
{
    const int tid=threadIdx.x, tx4=(tid&15)*4, ty4=(tid>>4)*4;
    const float4 bv=*(const float4*)(bias+tx4);
    #pragma unroll
    for(int r=0;r<4;++r){
        float4 o;
        o.x=accf(acc[r>>1][0],r&1)+bv.x; o.y=accf(acc[r>>1][1],r&1)+bv.y;
        o.z=accf(acc[r>>1][2],r&1)+bv.z; o.w=accf(acc[r>>1][3],r&1)+bv.w;
        *(float4*)(C+(size_t)(ty4+r)*ldc+tx4)=o;
    }
}

// ---------------- prep: embeddings + weight permutation + bias sums ----------------
__global__ void prep_k(const int* __restrict__ src,const int* __restrict__ dec,
    const float* __restrict__ emb,
    const float* eWih0,const float* eWhh0,const float* ebih0,const float* ebhh0,
    const float* eWih1,const float* eWhh1,const float* ebih1,const float* ebhh1,
    const float* dWih0,const float* dWhh0,const float* dbih0,const float* dbhh0,
    const float* dWih1,const float* dWhh1,const float* dbih1,const float* dbhh1)
{
    const int id=blockIdx.x*blockDim.x+threadIdx.x;
    const int stride=gridDim.x*blockDim.x;
    for(int i=id;i<S*B*E;i+=stride){
        const int j=i%E, b=(i/E)%B, t=i/(E*B);
        const int tok=src[b*S+t];
        const float v=tok?emb[(size_t)tok*E+j]:0.f;
        g_xs[((size_t)t*B+b)*E+j]=v;
        g_xs[(size_t)S*B*E+((size_t)(S-1-t)*B+b)*E+j]=v;
    }
    for(int i=id;i<T*B*E;i+=stride){
        const int j=i%E, b=(i/E)%B, t=i/(E*B);
        const int tok=dec[b*T+t];
        g_edec[((size_t)t*B+b)*E+j]=tok?emb[(size_t)tok*E+j]:0.f;
    }
    auto P=[&](float* dst,const float* s2,int WID,int ZG){
        const int tot=ZG*G*WID;
        for(int i=id;i<tot;i+=stride){
            const int z=i/(G*WID), r=i-z*(G*WID), p=r/WID, k=r-p*WID;
            dst[i]=s2[((size_t)z*G+(p&3)*H+(p>>2))*WID+k];
        }
    };
    P(g_wE0ih,eWih0,E,2);  P(g_wE0hh,eWhh0,H,2);
    P(g_wE1ih,eWih1,H2,2); P(g_wE1hh,eWhh1,H,2);
    P(g_wD0,dWih0,EH2,1);  P(g_wD0hh,dWhh0,H,1);
    P(g_wD1ih,dWih1,H,1);  P(g_wD1hh,dWhh1,H,1);
    auto PB=[&](float* dst,const float* b0,const float* b1,int ZG){
        for(int i=id;i<ZG*G;i+=stride){
            const int z=i/G, p=i-z*G, o=(p&3)*H+(p>>2);
            dst[i]=b0[z*G+o]+b1[z*G+o];
        }
    };
    PB(g_be0,ebih0,ebhh0,2); PB(g_be1,ebih1,ebhh1,2);
    PB(g_bd0,dbih0,dbhh0,1); PB(g_bd1,dbih1,dbhh1,1);
}

// ---------------- precompute GEMM ----------------
__global__ __launch_bounds__(256) void gemm2_k(
    const float* __restrict__ A,int lda,int K,
    const float* __restrict__ W,int ldw,
    const float* __restrict__ bias,float* __restrict__ C,int ldc,
    long long zsA,long long zsW,long long zsB,long long zsC)
{
    __shared__ __align__(16) float As[16][66];
    __shared__ __align__(16) ull   Bs[16][66];
    const int z=blockIdx.z;
    ull acc[2][4]={{0,0,0,0},{0,0,0,0}};
    gcore2(A+z*zsA+(size_t)blockIdx.y*64*lda, lda,
           W+z*zsW+(size_t)blockIdx.x*64*ldw, ldw, K, As,Bs,acc);
    store_out(acc, C+z*zsC+(size_t)blockIdx.y*64*ldc+blockIdx.x*64, ldc,
              bias+z*zsB+blockIdx.x*64);
}

// ---------------- persistent encoder layer: fused pointwise, c in regs ----------------
__global__ __launch_bounds__(NT) void enc_layer_k(
    const float* __restrict__ pre, const float* __restrict__ whp,
    float* __restrict__ ynorm, float* __restrict__ yrev,
    float* __restrict__ hsum, float* __restrict__ csum)
{
    __shared__ __align__(16) float As[16][66];
    __shared__ __align__(16) ull   Bs[16][66];
    const int cta=blockIdx.x, tid=threadIdx.x;
    unsigned ph=*(volatile unsigned*)&g_flag;
    for(int i=cta*NT+tid;i<2*B*H;i+=NB*NT) g_hb[0][i]=0.f;
    gbar(ph);
    const int dir=cta>>6, rr=cta&63, mt=rr>>5, nt=rr&31;
    const int tx=tid&15, tx4=tx*4, ty4=(tid>>4)*4;
    const int j=nt*16+tx;
    const float* Wt=whp+((size_t)dir*G+(size_t)nt*64)*H;
    float c[4]={0.f,0.f,0.f,0.f};
    #pragma unroll 1
    for(int s=0;s<S;++s){
        const int par=s&1;
        ull acc[2][4]={{0,0,0,0},{0,0,0,0}};
        gcore2(g_hb[par]+(size_t)dir*B*H+(size_t)mt*64*H, H, Wt, H, H, As,Bs,acc);
        const float* preT=pre+(((size_t)dir*S+s)*B+mt*64)*G+nt*64;
        float* hout=g_hb[par^1]+(size_t)dir*B*H;
        const int tt=dir?(S-1-s):s;
        #pragma unroll
        for(int r=0;r<4;++r){
            const int b=mt*64+ty4+r;
            const float4 pv=__ldcg((const float4*)(preT+(size_t)(ty4+r)*G+tx4));
            const float gi=accf(acc[r>>1][0],r&1)+pv.x;
            const float gf=accf(acc[r>>1][1],r&1)+pv.y;
            const float gg=accf(acc[r>>1][2],r&1)+pv.z;
            const float go=accf(acc[r>>1][3],r&1)+pv.w;
            const float cn=sigf(gf)*c[r]+sigf(gi)*tanhf(gg);
            c[r]=cn;
            const float hn=sigf(go)*tanhf(cn);
            hout[(size_t)b*H+j]=hn;
            ynorm[((size_t)tt*B+b)*H2+dir*H+j]=hn;
            if(yrev) yrev[((size_t)(S-1-tt)*B+b)*H2+dir*H+j]=hn;
        }
        gbar(ph);
    }
    #pragma unroll
    for(int r=0;r<4;++r)
        g_cst[(size_t)dir*B*H+(size_t)(mt*64+ty4+r)*H+j]=c[r];
    gbar(ph);
    for(int i=cta*NT+tid;i<B*H;i+=NB*NT){
        hsum[i]=__ldcg(&g_hb[0][i])+__ldcg(&g_hb[0][B*H+i]);
        csum[i]=__ldcg(&g_cst[i])+__ldcg(&g_cst[B*H+i]);
    }
}

// ---------------- persistent decoder ----------------
__global__ __launch_bounds__(NT) void dec_k(
    const float* __restrict__ pre, const int* __restrict__ src,
    const float* __restrict__ enc,
    const float* __restrict__ Wq, const float* __restrict__ bq,
    const float* __restrict__ Wout, const float* __restrict__ bout,
    float* __restrict__ out)
{
    __shared__ __align__(16) float As[16][66];
    __shared__ __align__(16) ull   Bs[16][66];
    __shared__ float qs[H2];
    __shared__ float sc[S];
    __shared__ float red[8];
    __shared__ float s_max, s_sum;
    const int cta=blockIdx.x, tid=threadIdx.x, lane=tid&31, w=tid>>5;
    const int tx=tid&15, tx4=tx*4, ty4=(tid>>4)*4;
    unsigned ph=*(volatile unsigned*)&g_flag;

    for(int i=cta*NT+tid;i<B*H;i+=NB*NT){
        g_d0hb[1][i]=g_h0i[i];
        g_d1hb[1][i]=g_h1i[i];
    }
    float c[4];
    {
        const int cc=cta&63, mt=cc>>5, nt=cc&31, u=nt*16+tx;
        const float* cs=(cta<64)?g_c0i:g_c1i;
        #pragma unroll
        for(int r=0;r<4;++r) c[r]=cs[(size_t)(mt*64+ty4+r)*H+u];
    }
    gbar(ph);

    #pragma unroll 1
    for(int t=0;t<T;++t){
        const int par=t&1;
        const float* h1p=g_d1hb[par^1];
        // P1: q (CTAs 0..31) + logits t-1 (CTAs 32..47)
        if(cta<32){
            const int mt=cta>>4, nt=cta&15;
            ull acc[2][4]={{0,0,0,0},{0,0,0,0}};
            gcore2(h1p+(size_t)mt*64*H, H, Wq+(size_t)nt*64*H, H, H, As,Bs,acc);
            store_out(acc, g_q+(size_t)mt*64*H2+nt*64, H2, bq+nt*64);
        } else if(cta<48 && t>0){
            const int ct=cta-32, mt=ct>>3, nt=ct&7;
            ull acc[2][4]={{0,0,0,0},{0,0,0,0}};
            gcore2(h1p+(size_t)mt*64*H, H, Wout+(size_t)nt*64*H, H, H, As,Bs,acc);
            store_out(acc, out+(size_t)mt*64*(T*V)+(size_t)(t-1)*V+nt*64, T*V, bout+nt*64);
        }
        gbar(ph);
        // P2: attention (CTA = batch)
        {
            const int b=cta;
            for(int k=tid*4;k<H2;k+=NT*4)
                *(float4*)&qs[k]=__ldcg((const float4*)(g_q+(size_t)b*H2+k));
            __syncthreads();
            for(int s=w;s<S;s+=8){
                const float* eb=enc+((size_t)s*B+b)*H2;
                float sum=0.f;
                #pragma unroll
                for(int k=lane*4;k<H2;k+=128){
                    const float4 e=*(const float4*)(eb+k);
                    sum+=e.x*qs[k]+e.y*qs[k+1]+e.z*qs[k+2]+e.w*qs[k+3];
                }
                #pragma unroll
                for(int o=16;o;o>>=1) sum+=__shfl_xor_sync(0xffffffffu,sum,o);
                if(lane==0) sc[s]=(src[b*S+s]!=0)?sum:-1e9f;
            }
            __syncthreads();
            const float v=sc[tid];
            float m=v;
            #pragma unroll
            for(int o=16;o;o>>=1) m=fmaxf(m,__shfl_xor_sync(0xffffffffu,m,o));
            if(lane==0) red[w]=m;
            __syncthreads();
            if(tid==0){
                float mm=red[0];
                #pragma unroll
                for(int i=1;i<8;++i) mm=fmaxf(mm,red[i]);
                s_max=mm;
            }
            __syncthreads();
            const float ev=expf(v-s_max);
            float sum=ev;
            #pragma unroll
            for(int o=16;o;o>>=1) sum+=__shfl_xor_sync(0xffffffffu,sum,o);
            if(lane==0) red[w]=sum;
            __syncthreads();
            if(tid==0){
                float ss=0.f;
                #pragma unroll
                for(int i=0;i<8;++i) ss+=red[i];
                s_sum=ss;
            }
            __syncthreads();
            sc[tid]=ev/s_sum;
            __syncthreads();
            const int k4=tid*4;
            float4 a={0.f,0.f,0.f,0.f};
            const float* ep=enc+(size_t)b*H2+k4;
            #pragma unroll 4
            for(int s=0;s<S;++s){
                const float p=sc[s];
                const float4 e=*(const float4*)(ep+(size_t)s*B*H2);
                a.x+=p*e.x; a.y+=p*e.y; a.z+=p*e.z; a.w+=p*e.w;
            }
            *(float4*)(g_ctx+(size_t)b*H2+k4)=a;
        }
        gbar(ph);
        // P3: cell0 fused (CTAs 0..63)
        if(cta<64){
            const int mt=cta>>5, nt=cta&31, u=nt*16+tx;
            ull acc[2][4]={{0,0,0,0},{0,0,0,0}};
            gcore2(g_ctx+(size_t)mt*64*H2, H2, g_wD0+E+(size_t)nt*64*EH2, EH2, H2, As,Bs,acc);
            gcore2(g_d0hb[par^1]+(size_t)mt*64*H, H, g_wD0hh+(size_t)nt*64*H, H, H, As,Bs,acc);
            const float* preT=pre+((size_t)t*B+mt*64)*G+nt*64;
            float* hout=g_d0hb[par];
            #pragma unroll
            for(int r=0;r<4;++r){
                const int b=mt*64+ty4+r;
                const float4 pv=__ldcg((const float4*)(preT+(size_t)(ty4+r)*G+tx4));
                const float gi=accf(acc[r>>1][0],r&1)+pv.x;
                const float gf=accf(acc[r>>1][1],r&1)+pv.y;
                const float gg=accf(acc[r>>1][2],r&1)+pv.z;
                const float go=accf(acc[r>>1][3],r&1)+pv.w;
                const float cn=sigf(gf)*c[r]+sigf(gi)*tanhf(gg);
                c[r]=cn;
                hout[(size_t)b*H+u]=sigf(go)*tanhf(cn);
            }
        }
        gbar(ph);
        // P4: cell1 fused (CTAs 64..127)
        if(cta>=64){
            const int cc=cta-64, mt=cc>>5, nt=cc&31, u=nt*16+tx;
            ull acc[2][4]={{0,0,0,0},{0,0,0,0}};
            gcore2(g_d0hb[par]+(size_t)mt*64*H, H, g_wD1ih+(size_t)nt*64*H, H, H, As,Bs,acc);
            gcore2(h1p+(size_t)mt*64*H, H, g_wD1hh+(size_t)nt*64*H, H, H, As,Bs,acc);
            const float4 bv=*(const float4*)(g_bd1+nt*64+tx4);
            float* hout=g_d1hb[par];
            #pragma unroll
            for(int r=0;r<4;++r){
                const int b=mt*64+ty4+r;
                const float gi=accf(acc[r>>1][0],r&1)+bv.x;
                const float gf=accf(acc[r>>1][1],r&1)+bv.y;
                const float gg=accf(acc[r>>1][2],r&1)+bv.z;
                const float go=accf(acc[r>>1][3],r&1)+bv.w;
                const float cn=sigf(gf)*c[r]+sigf(gi)*tanhf(gg);
                c[r]=cn;
                hout[(size_t)b*H+u]=sigf(go)*tanhf(cn);
            }
        }
        gbar(ph);
    }
    // final logits (t = T-1); last d1h written to parity (T-1)&1 = 1
    if(cta>=32&&cta<48){
        const int ct=cta-32, mt=ct>>3, nt=ct&7;
        ull acc[2][4]={{0,0,0,0},{0,0,0,0}};
        gcore2(g_d1hb[1]+(size_t)mt*64*H, H, Wout+(size_t)nt*64*H, H, H, As,Bs,acc);
        store_out(acc, out+(size_t)mt*64*(T*V)+(size_t)(T-1)*V+nt*64, T*V, bout+nt*64);
    }
}

// ---------------- host ----------------
static inline void* sym(const void* s){ void* p=nullptr; cudaGetSymbolAddress(&p,s); return p; }

extern "C" void kernel_launch(void* const* d_in, const int* in_sizes, int n_in,
                              void* d_out, int out_size)
{
    (void)in_sizes;(void)n_in;(void)out_size;
    const int* src=(const int*)d_in[0];
    const int* decin=(const int*)d_in[1];
    const float* emb=(const float*)d_in[2];
    const float* eWih0=(const float*)d_in[3];
    const float* eWhh0=(const float*)d_in[4];
    const float* ebih0=(const float*)d_in[5];
    const float* ebhh0=(const float*)d_in[6];
    const float* eWih1=(const float*)d_in[7];
    const float* eWhh1=(const float*)d_in[8];
    const float* ebih1=(const float*)d_in[9];
    const float* ebhh1=(const float*)d_in[10];
    const float* dWih0=(const float*)d_in[11];
    const float* dWhh0=(const float*)d_in[12];
    const float* dbih0=(const float*)d_in[13];
    const float* dbhh0=(const float*)d_in[14];
    const float* dWih1=(const float*)d_in[15];
    const float* dWhh1=(const float*)d_in[16];
    const float* dbih1=(const float*)d_in[17];
    const float* dbhh1=(const float*)d_in[18];
    const float* Wq=(const float*)d_in[19];
    const float* bq=(const float*)d_in[20];
    const float* Wout=(const float*)d_in[21];
    const float* bout=(const float*)d_in[22];
    float* out=(float*)d_out;

    float* xs=(float*)sym(g_xs);    float* pre=(float*)sym(g_pre);
    float* y0=(float*)sym(g_y0);    float* enc=(float*)sym(g_enc);
    float* edec=(float*)sym(g_edec);
    float* wE0ih=(float*)sym(g_wE0ih); float* wE0hh=(float*)sym(g_wE0hh);
    float* wE1ih=(float*)sym(g_wE1ih); float* wE1hh=(float*)sym(g_wE1hh);
    float* wD0=(float*)sym(g_wD0);
    float* be0=(float*)sym(g_be0);  float* be1=(float*)sym(g_be1);
    float* bd0=(float*)sym(g_bd0);
    float* h0i=(float*)sym(g_h0i);  float* c0i=(float*)sym(g_c0i);
    float* h1i=(float*)sym(g_h1i);  float* c1i=(float*)sym(g_c1i);

    prep_k<<<512,NT>>>(src,decin,emb,
        eWih0,eWhh0,ebih0,ebhh0, eWih1,eWhh1,ebih1,ebhh1,
        dWih0,dWhh0,dbih0,dbhh0, dWih1,dWhh1,dbih1,dbhh1);

    const long long SBG=(long long)S*B*G;
    // encoder layer0 input projections
    gemm2_k<<<dim3(32,(S*B)/64,2),256>>>(xs,E,E, wE0ih,E, be0, pre,G,
        (long long)S*B*E,(long long)G*E,G,SBG);
    enc_layer_k<<<NB,NT>>>(pre, wE0hh, y0, y0+(size_t)S*B*H2, h0i,c0i);
    // encoder layer1 input projections
    gemm2_k<<<dim3(32,(S*B)/64,2),256>>>(y0,H2,H2, wE1ih,H2, be1, pre,G,
        (long long)S*B*H2,(long long)G*H2,G,SBG);
    enc_layer_k<<<NB,NT>>>(pre, wE1hh, enc, nullptr, h1i,c1i);
    // decoder embedding projection (emb cols of dWih0, biases folded)
    gemm2_k<<<dim3(32,(T*B)/64,1),256>>>(edec,E,E, wD0,EH2, bd0, pre,G, 0,0,0,0);
    // decoder
    dec_k<<<NB,NT>>>(pre, src, enc, Wq,bq, Wout,bout, out);
}

// round 9
// speedup vs baseline: 1.6348x; 1.6348x over previous
#include <cuda_runtime.h>
#include <math.h>
typedef unsigned long long ull;

constexpr int B=128,S=256,T=256,V=512,E=256,H=512,G=2048,H2=1024,EH2=1280;
constexpr int NB=128, NT=256;

__device__ __align__(256) float g_xs[(size_t)2*S*B*E];
__device__ __align__(256) float g_edec[(size_t)T*B*E];
__device__ __align__(256) float g_pre[(size_t)2*S*B*G];
__device__ __align__(256) float g_y0[(size_t)2*S*B*H2];
__device__ __align__(256) float g_enc[(size_t)S*B*H2];
__device__ __align__(256) float g_hb[2][2*B*H];
__device__ __align__(256) float g_cst[2*B*H];
__device__ __align__(256) float g_q[B*H2];
__device__ __align__(256) float g_ctx[B*H2];
__device__ __align__(256) float g_d0hb[2][B*H];
__device__ __align__(256) float g_d1hb[2][B*H];
__device__ __align__(256) float g_h0i[B*H];
__device__ __align__(256) float g_c0i[B*H];
__device__ __align__(256) float g_h1i[B*H];
__device__ __align__(256) float g_c1i[B*H];
// permuted weights (row g*H+j -> j*4+g) and permuted summed biases
__device__ __align__(256) float g_wE0ih[2*G*E];
__device__ __align__(256) float g_wE0hh[2*G*H];
__device__ __align__(256) float g_wE1ih[2*G*H2];
__device__ __align__(256) float g_wE1hh[2*G*H];
__device__ __align__(256) float g_wD0[G*EH2];
__device__ __align__(256) float g_wD0hh[G*H];
__device__ __align__(256) float g_wD1ih[G*H];
__device__ __align__(256) float g_wD1hh[G*H];
__device__ __align__(256) float g_be0[2*G];
__device__ __align__(256) float g_be1[2*G];
__device__ __align__(256) float g_bd0[G];
__device__ __align__(256) float g_bd1[G];

__device__ unsigned g_cnt, g_flag;

__device__ __forceinline__ void gbar(unsigned& phase)
{
    __syncthreads();
    if (threadIdx.x == 0) {
        __threadfence();
        const unsigned target = phase + 1;
        if (atomicAdd(&g_cnt, 1) == NB - 1) {
            g_cnt = 0; __threadfence();
            atomicExch(&g_flag, target);
        } else {
            while (*(volatile unsigned*)&g_flag < target) { __nanosleep(32); }
            __threadfence();
        }
        phase = target;
    }
    __syncthreads();
}

union UPair { ull u; float2 f; };
__device__ __forceinline__ ull dupf(float x){ ull r; asm("mov.b64 %0,{%1,%1};":"=l"(r):"f"(x)); return r; }
#define FMA2(d,a,b) asm("fma.rn.f32x2 %0,%1,%2,%0;":"+l"(d):"l"(a),"l"(b))
__device__ __forceinline__ float accf(ull a,int h){ UPair u; u.u=a; return h?u.f.y:u.f.x; }
__device__ __forceinline__ float sigf(float x){ return 1.f/(1.f+expf(-x)); }

// ---------------- 64x64 tile core, thread tile 2 rows x 8 cols ----------------
// acc[r][p]: r in {0,1} = rows ty*2+r; p in {0,1} -> col-pairs {tx*4,tx*4+1},{tx*4+2,+3};
//            p in {2,3} -> {32+tx*4,...}. B un-duplicated in smem; f32x2 pairs natural.
// Double-buffered smem, one sync per 16-k chunk (even chunk counts only: K%32==0).
__device__ __forceinline__ void gcore3(const float* __restrict__ A,int lda,
    const float* __restrict__ W,int ldw,int K,
    float (*As)[66], float (*Bs)[68], ull acc[2][4])
{
    const int tid=threadIdx.x;
    const int tx=tid&7, ty=tid>>3;
    const int lr=tid>>2, lk=(tid&3)*4;
    const float* ap=A+(size_t)lr*lda+lk;
    const float* wp=W+(size_t)lr*ldw+lk;
    float4 pa=__ldcg((const float4*)ap);
    float4 pw=*(const float4*)wp;
    int buf=0;
    #pragma unroll 1
    for(int kk=0;kk<K;kk+=16){
        const int b16=buf<<4;
        As[b16+lk+0][lr]=pa.x; As[b16+lk+1][lr]=pa.y;
        As[b16+lk+2][lr]=pa.z; As[b16+lk+3][lr]=pa.w;
        Bs[b16+lk+0][lr]=pw.x; Bs[b16+lk+1][lr]=pw.y;
        Bs[b16+lk+2][lr]=pw.z; Bs[b16+lk+3][lr]=pw.w;
        __syncthreads();
        if(kk+16<K){ pa=__ldcg((const float4*)(ap+kk+16)); pw=*(const float4*)(wp+kk+16); }
        #pragma unroll
        for(int k=0;k<16;++k){
            const float2 a=*(const float2*)&As[b16+k][ty*2];
            const ull A0=dupf(a.x), A1=dupf(a.y);
            const ulonglong2 bL=*(const ulonglong2*)&Bs[b16+k][tx*4];
            const ulonglong2 bH=*(const ulonglong2*)&Bs[b16+k][32+tx*4];
            FMA2(acc[0][0],A0,bL.x); FMA2(acc[0][1],A0,bL.y);
            FMA2(acc[0][2],A0,bH.x); FMA2(acc[0][3],A0,bH.y);
            FMA2(acc[1][0],A1,bL.x); FMA2(acc[1][1],A1,bL.y);
            FMA2(acc[1][2],A1,bH.x); FMA2(acc[1][3],A1,bH.y);
        }
        buf^=1;
    }
}

// store with tile-relative bias (bias pre-offset by N-tile base, 64 wide)
__device__ __forceinline__ void store_out(ull acc[2][4], float* __restrict__ C,
                                          int ldc, const float* __restrict__ bias)
{
    const int tid=threadIdx.x, tx=tid&7, ty=tid>>3;
    const float4 bL=*(const float4*)(bias+tx*4);
    const float4 bH=*(const float4*)(bias+32+tx*4);
    #pragma unroll
    for(int r=0;r<2;++r){
        const int row=ty*2+r;
        float4 oL, oH;
        oL.x=accf(acc[r][0],0)+bL.x; oL.y=accf(acc[r][0],1)+bL.y;
        oL.z=accf(acc[r][1],0)+bL.z; oL.w=accf(acc[r][1],1)+bL.w;
        oH.x=accf(acc[r][2],0)+bH.x; oH.y=accf(acc[r][2],1)+bH.y;
        oH.z=accf(acc[r][3],0)+bH.z; oH.w=accf(acc[r][3],1)+bH.w;
        *(float4*)(C+(size_t)row*ldc+tx*4)=oL;
        *(float4*)(C+(size_t)row*ldc+32+tx*4)=oH;
    }
}

// ---------------- prep: embeddings + weight permutation + bias sums ----------------
__global__ void prep_k(const int* __restrict__ src,const int* __restrict__ dec,
    const float* __restrict__ emb,
    const float* eWih0,const float* eWhh0,const float* ebih0,const float* ebhh0,
    const float* eWih1,const float* eWhh1,const float* ebih1,const float* ebhh1,
    const float* dWih0,const float* dWhh0,const float* dbih0,const float* dbhh0,
    const float* dWih1,const float* dWhh1,const float* dbih1,const float* dbhh1)
{
    const int id=blockIdx.x*blockDim.x+threadIdx.x;
    const int stride=gridDim.x*blockDim.x;
    for(int i=id;i<S*B*E;i+=stride){
        const int j=i%E, b=(i/E)%B, t=i/(E*B);
        const int tok=src[b*S+t];
        const float v=tok?emb[(size_t)tok*E+j]:0.f;
        g_xs[((size_t)t*B+b)*E+j]=v;
        g_xs[(size_t)S*B*E+((size_t)(S-1-t)*B+b)*E+j]=v;
    }
    for(int i=id;i<T*B*E;i+=stride){
        const int j=i%E, b=(i/E)%B, t=i/(E*B);
        const int tok=dec[b*T+t];
        g_edec[((size_t)t*B+b)*E+j]=tok?emb[(size_t)tok*E+j]:0.f;
    }
    auto P=[&](float* dst,const float* s2,int WID,int ZG){
        const int tot=ZG*G*WID;
        for(int i=id;i<tot;i+=stride){
            const int z=i/(G*WID), r=i-z*(G*WID), p=r/WID, k=r-p*WID;
            dst[i]=s2[((size_t)z*G+(p&3)*H+(p>>2))*WID+k];
        }
    };
    P(g_wE0ih,eWih0,E,2);  P(g_wE0hh,eWhh0,H,2);
    P(g_wE1ih,eWih1,H2,2); P(g_wE1hh,eWhh1,H,2);
    P(g_wD0,dWih0,EH2,1);  P(g_wD0hh,dWhh0,H,1);
    P(g_wD1ih,dWih1,H,1);  P(g_wD1hh,dWhh1,H,1);
    auto PB=[&](float* dst,const float* b0,const float* b1,int ZG){
        for(int i=id;i<ZG*G;i+=stride){
            const int z=i/G, p=i-z*G, o=(p&3)*H+(p>>2);
            dst[i]=b0[z*G+o]+b1[z*G+o];
        }
    };
    PB(g_be0,ebih0,ebhh0,2); PB(g_be1,ebih1,ebhh1,2);
    PB(g_bd0,dbih0,dbhh0,1); PB(g_bd1,dbih1,dbhh1,1);
}

// ---------------- precompute GEMM ----------------
__global__ __launch_bounds__(256,4) void gemm2_k(
    const float* __restrict__ A,int lda,int K,
    const float* __restrict__ W,int ldw,
    const float* __restrict__ bias,float* __restrict__ C,int ldc,
    long long zsA,long long zsW,long long zsB,long long zsC)
{
    __shared__ __align__(16) float As[32][66];
    __shared__ __align__(16) float Bs[32][68];
    const int z=blockIdx.z;
    ull acc[2][4]={{0,0,0,0},{0,0,0,0}};
    gcore3(A+z*zsA+(size_t)blockIdx.y*64*lda, lda,
           W+z*zsW+(size_t)blockIdx.x*64*ldw, ldw, K, As,Bs,acc);
    store_out(acc, C+z*zsC+(size_t)blockIdx.y*64*ldc+blockIdx.x*64, ldc,
              bias+z*zsB+blockIdx.x*64);
}

// ---------------- persistent encoder layer: fused pointwise, c in regs ----------------
__global__ __launch_bounds__(NT,1) void enc_layer_k(
    const float* __restrict__ pre, const float* __restrict__ whp,
    float* __restrict__ ynorm, float* __restrict__ yrev,
    float* __restrict__ hsum, float* __restrict__ csum)
{
    __shared__ __align__(16) float As[32][66];
    __shared__ __align__(16) float Bs[32][68];
    const int cta=blockIdx.x, tid=threadIdx.x;
    unsigned ph=*(volatile unsigned*)&g_flag;
    for(int i=cta*NT+tid;i<2*B*H;i+=NB*NT) g_hb[0][i]=0.f;
    gbar(ph);
    const int dir=cta>>6, rr=cta&63, mt=rr>>5, nt=rr&31;
    const int tx=tid&7, ty=tid>>3;
    const float* Wt=whp+((size_t)dir*G+(size_t)nt*64)*H;
    float c[2][2]={{0.f,0.f},{0.f,0.f}};
    #pragma unroll 1
    for(int s=0;s<S;++s){
        const int par=s&1;
        ull acc[2][4]={{0,0,0,0},{0,0,0,0}};
        gcore3(g_hb[par]+(size_t)dir*B*H+(size_t)mt*64*H, H, Wt, H, H, As,Bs,acc);
        const float* preT=pre+(((size_t)dir*S+s)*B+mt*64)*G+nt*64;
        float* hout=g_hb[par^1]+(size_t)dir*B*H;
        const int tt=dir?(S-1-s):s;
        #pragma unroll
        for(int r=0;r<2;++r){
            const int row=ty*2+r;
            const int b=mt*64+row;
            #pragma unroll
            for(int h=0;h<2;++h){
                const float4 pv=__ldcg((const float4*)(preT+(size_t)row*G+h*32+tx*4));
                const float gi=accf(acc[r][2*h+0],0)+pv.x;
                const float gf=accf(acc[r][2*h+0],1)+pv.y;
                const float gg=accf(acc[r][2*h+1],0)+pv.z;
                const float go=accf(acc[r][2*h+1],1)+pv.w;
                const float cn=sigf(gf)*c[r][h]+sigf(gi)*tanhf(gg);
                c[r][h]=cn;
                const float hn=sigf(go)*tanhf(cn);
                const int u=nt*16+h*8+tx;
                hout[(size_t)b*H+u]=hn;
                ynorm[((size_t)tt*B+b)*H2+dir*H+u]=hn;
                if(yrev) yrev[((size_t)(S-1-tt)*B+b)*H2+dir*H+u]=hn;
            }
        }
        gbar(ph);
    }
    #pragma unroll
    for(int r=0;r<2;++r)
        #pragma unroll
        for(int h=0;h<2;++h)
            g_cst[(size_t)dir*B*H+(size_t)(mt*64+ty*2+r)*H+nt*16+h*8+tx]=c[r][h];
    gbar(ph);
    for(int i=cta*NT+tid;i<B*H;i+=NB*NT){
        hsum[i]=__ldcg(&g_hb[0][i])+__ldcg(&g_hb[0][B*H+i]);
        csum[i]=__ldcg(&g_cst[i])+__ldcg(&g_cst[B*H+i]);
    }
}

// ---------------- persistent decoder ----------------
__global__ __launch_bounds__(NT,1) void dec_k(
    const float* __restrict__ pre, const int* __restrict__ src,
    const float* __restrict__ enc,
    const float* __restrict__ Wq, const float* __restrict__ bq,
    const float* __restrict__ Wout, const float* __restrict__ bout,
    float* __restrict__ out)
{
    __shared__ __align__(16) float As[32][66];
    __shared__ __align__(16) float Bs[32][68];
    __shared__ float qs[H2];
    __shared__ float sc[S];
    __shared__ float red[8];
    __shared__ float s_max, s_sum;
    const int cta=blockIdx.x, tid=threadIdx.x, lane=tid&31, w=tid>>5;
    const int tx=tid&7, ty=tid>>3;
    unsigned ph=*(volatile unsigned*)&g_flag;

    for(int i=cta*NT+tid;i<B*H;i+=NB*NT){
        g_d0hb[1][i]=g_h0i[i];
        g_d1hb[1][i]=g_h1i[i];
    }
    float c[2][2];
    {
        const int cc=cta&63, mt=cc>>5, nt=cc&31;
        const float* cs=(cta<64)?g_c0i:g_c1i;
        #pragma unroll
        for(int r=0;r<2;++r)
            #pragma unroll
            for(int h=0;h<2;++h)
                c[r][h]=cs[(size_t)(mt*64+ty*2+r)*H+nt*16+h*8+tx];
    }
    gbar(ph);

    #pragma unroll 1
    for(int t=0;t<T;++t){
        const int par=t&1;
        const float* h1p=g_d1hb[par^1];
        // P1: q (CTAs 0..31) + logits t-1 (CTAs 32..47)
        if(cta<32){
            const int mt=cta>>4, nt=cta&15;
            ull acc[2][4]={{0,0,0,0},{0,0,0,0}};
            gcore3(h1p+(size_t)mt*64*H, H, Wq+(size_t)nt*64*H, H, H, As,Bs,acc);
            store_out(acc, g_q+(size_t)mt*64*H2+nt*64, H2, bq+nt*64);
        } else if(cta<48 && t>0){
            const int ct=cta-32, mt=ct>>3, nt=ct&7;
            ull acc[2][4]={{0,0,0,0},{0,0,0,0}};
            gcore3(h1p+(size_t)mt*64*H, H, Wout+(size_t)nt*64*H, H, H, As,Bs,acc);
            store_out(acc, out+(size_t)mt*64*(T*V)+(size_t)(t-1)*V+nt*64, T*V, bout+nt*64);
        }
        gbar(ph);
        // P2: attention (CTA = batch)
        {
            const int b=cta;
            for(int k=tid*4;k<H2;k+=NT*4)
                *(float4*)&qs[k]=__ldcg((const float4*)(g_q+(size_t)b*H2+k));
            __syncthreads();
            for(int s=w;s<S;s+=8){
                const float* eb=enc+((size_t)s*B+b)*H2;
                float sum=0.f;
                #pragma unroll
                for(int k=lane*4;k<H2;k+=128){
                    const float4 e=*(const float4*)(eb+k);
                    sum+=e.x*qs[k]+e.y*qs[k+1]+e.z*qs[k+2]+e.w*qs[k+3];
                }
                #pragma unroll
                for(int o=16;o;o>>=1) sum+=__shfl_xor_sync(0xffffffffu,sum,o);
                if(lane==0) sc[s]=(src[b*S+s]!=0)?sum:-1e9f;
            }
            __syncthreads();
            const float v=sc[tid];
            float m=v;
            #pragma unroll
            for(int o=16;o;o>>=1) m=fmaxf(m,__shfl_xor_sync(0xffffffffu,m,o));
            if(lane==0) red[w]=m;
            __syncthreads();
            if(tid==0){
                float mm=red[0];
                #pragma unroll
                for(int i=1;i<8;++i) mm=fmaxf(mm,red[i]);
                s_max=mm;
            }
            __syncthreads();
            const float ev=expf(v-s_max);
            float sum=ev;
            #pragma unroll
            for(int o=16;o;o>>=1) sum+=__shfl_xor_sync(0xffffffffu,sum,o);
            if(lane==0) red[w]=sum;
            __syncthreads();
            if(tid==0){
                float ss=0.f;
                #pragma unroll
                for(int i=0;i<8;++i) ss+=red[i];
                s_sum=ss;
            }
            __syncthreads();
            sc[tid]=ev/s_sum;
            __syncthreads();
            const int k4=tid*4;
            float4 a={0.f,0.f,0.f,0.f};
            const float* ep=enc+(size_t)b*H2+k4;
            #pragma unroll 4
            for(int s=0;s<S;++s){
                const float p=sc[s];
                const float4 e=*(const float4*)(ep+(size_t)s*B*H2);
                a.x+=p*e.x; a.y+=p*e.y; a.z+=p*e.z; a.w+=p*e.w;
            }
            *(float4*)(g_ctx+(size_t)b*H2+k4)=a;
        }
        gbar(ph);
        // P3: cell0 fused (CTAs 0..63)
        if(cta<64){
            const int mt=cta>>5, nt=cta&31;
            ull acc[2][4]={{0,0,0,0},{0,0,0,0}};
            gcore3(g_ctx+(size_t)mt*64*H2, H2, g_wD0+E+(size_t)nt*64*EH2, EH2, H2, As,Bs,acc);
            gcore3(g_d0hb[par^1]+(size_t)mt*64*H, H, g_wD0hh+(size_t)nt*64*H, H, H, As,Bs,acc);
            const float* preT=pre+((size_t)t*B+mt*64)*G+nt*64;
            float* hout=g_d0hb[par];
            #pragma unroll
            for(int r=0;r<2;++r){
                const int row=ty*2+r;
                const int b=mt*64+row;
                #pragma unroll
                for(int h=0;h<2;++h){
                    const float4 pv=__ldcg((const float4*)(preT+(size_t)row*G+h*32+tx*4));
                    const float gi=accf(acc[r][2*h+0],0)+pv.x;
                    const float gf=accf(acc[r][2*h+0],1)+pv.y;
                    const float gg=accf(acc[r][2*h+1],0)+pv.z;
                    const float go=accf(acc[r][2*h+1],1)+pv.w;
                    const float cn=sigf(gf)*c[r][h]+sigf(gi)*tanhf(gg);
                    c[r][h]=cn;
                    hout[(size_t)b*H+nt*16+h*8+tx]=sigf(go)*tanhf(cn);
                }
            }
        }
        gbar(ph);
        // P4: cell1 fused (CTAs 64..127)
        if(cta>=64){
            const int cc=cta-64, mt=cc>>5, nt=cc&31;
            ull acc[2][4]={{0,0,0,0},{0,0,0,0}};
            gcore3(g_d0hb[par]+(size_t)mt*64*H, H, g_wD1ih+(size_t)nt*64*H, H, H, As,Bs,acc);
            gcore3(h1p+(size_t)mt*64*H, H, g_wD1hh+(size_t)nt*64*H, H, H, As,Bs,acc);
            float* hout=g_d1hb[par];
            const float4 bL=*(const float4*)(g_bd1+nt*64+tx*4);
            const float4 bH=*(const float4*)(g_bd1+nt*64+32+tx*4);
            #pragma unroll
            for(int r=0;r<2;++r){
                const int b=mt*64+ty*2+r;
                #pragma unroll
                for(int h=0;h<2;++h){
                    const float4 bv=h?bH:bL;
                    const float gi=accf(acc[r][2*h+0],0)+bv.x;
                    const float gf=accf(acc[r][2*h+0],1)+bv.y;
                    const float gg=accf(acc[r][2*h+1],0)+bv.z;
                    const float go=accf(acc[r][2*h+1],1)+bv.w;
                    const float cn=sigf(gf)*c[r][h]+sigf(gi)*tanhf(gg);
                    c[r][h]=cn;
                    hout[(size_t)b*H+nt*16+h*8+tx]=sigf(go)*tanhf(cn);
                }
            }
        }
        gbar(ph);
    }
    // final logits (t = T-1); last d1h written to parity (T-1)&1 = 1
    if(cta>=32&&cta<48){
        const int ct=cta-32, mt=ct>>3, nt=ct&7;
        ull acc[2][4]={{0,0,0,0},{0,0,0,0}};
        gcore3(g_d1hb[1]+(size_t)mt*64*H, H, Wout+(size_t)nt*64*H, H, H, As,Bs,acc);
        store_out(acc, out+(size_t)mt*64*(T*V)+(size_t)(T-1)*V+nt*64, T*V, bout+nt*64);
    }
}

// ---------------- host ----------------
static inline void* sym(const void* s){ void* p=nullptr; cudaGetSymbolAddress(&p,s); return p; }

extern "C" void kernel_launch(void* const* d_in, const int* in_sizes, int n_in,
                              void* d_out, int out_size)
{
    (void)in_sizes;(void)n_in;(void)out_size;
    const int* src=(const int*)d_in[0];
    const int* decin=(const int*)d_in[1];
    const float* emb=(const float*)d_in[2];
    const float* eWih0=(const float*)d_in[3];
    const float* eWhh0=(const float*)d_in[4];
    const float* ebih0=(const float*)d_in[5];
    const float* ebhh0=(const float*)d_in[6];
    const float* eWih1=(const float*)d_in[7];
    const float* eWhh1=(const float*)d_in[8];
    const float* ebih1=(const float*)d_in[9];
    const float* ebhh1=(const float*)d_in[10];
    const float* dWih0=(const float*)d_in[11];
    const float* dWhh0=(const float*)d_in[12];
    const float* dbih0=(const float*)d_in[13];
    const float* dbhh0=(const float*)d_in[14];
    const float* dWih1=(const float*)d_in[15];
    const float* dWhh1=(const float*)d_in[16];
    const float* dbih1=(const float*)d_in[17];
    const float* dbhh1=(const float*)d_in[18];
    const float* Wq=(const float*)d_in[19];
    const float* bq=(const float*)d_in[20];
    const float* Wout=(const float*)d_in[21];
    const float* bout=(const float*)d_in[22];
    float* out=(float*)d_out;

    float* xs=(float*)sym(g_xs);    float* pre=(float*)sym(g_pre);
    float* y0=(float*)sym(g_y0);    float* enc=(float*)sym(g_enc);
    float* edec=(float*)sym(g_edec);
    float* wE0ih=(float*)sym(g_wE0ih); float* wE0hh=(float*)sym(g_wE0hh);
    float* wE1ih=(float*)sym(g_wE1ih); float* wE1hh=(float*)sym(g_wE1hh);
    float* wD0=(float*)sym(g_wD0);
    float* be0=(float*)sym(g_be0);  float* be1=(float*)sym(g_be1);
    float* bd0=(float*)sym(g_bd0);
    float* h0i=(float*)sym(g_h0i);  float* c0i=(float*)sym(g_c0i);
    float* h1i=(float*)sym(g_h1i);  float* c1i=(float*)sym(g_c1i);

    prep_k<<<512,NT>>>(src,decin,emb,
        eWih0,eWhh0,ebih0,ebhh0, eWih1,eWhh1,ebih1,ebhh1,
        dWih0,dWhh0,dbih0,dbhh0, dWih1,dWhh1,dbih1,dbhh1);

    const long long SBG=(long long)S*B*G;
    // encoder layer0 input projections
    gemm2_k<<<dim3(32,(S*B)/64,2),256>>>(xs,E,E, wE0ih,E, be0, pre,G,
        (long long)S*B*E,(long long)G*E,G,SBG);
    enc_layer_k<<<NB,NT>>>(pre, wE0hh, y0, y0+(size_t)S*B*H2, h0i,c0i);
    // encoder layer1 input projections
    gemm2_k<<<dim3(32,(S*B)/64,2),256>>>(y0,H2,H2, wE1ih,H2, be1, pre,G,
        (long long)S*B*H2,(long long)G*H2,G,SBG);
    enc_layer_k<<<NB,NT>>>(pre, wE1hh, enc, nullptr, h1i,c1i);
    // decoder embedding projection (emb cols of dWih0, biases folded)
    gemm2_k<<<dim3(32,(T*B)/64,1),256>>>(edec,E,E, wD0,EH2, bd0, pre,G, 0,0,0,0);
    // decoder
    dec_k<<<NB,NT>>>(pre, src, enc, Wq,bq, Wout,bout, out);
}

// round 10
// speedup vs baseline: 2.2908x; 1.4013x over previous
#include <cuda_runtime.h>
#include <cuda_bf16.h>
#include <math.h>
typedef unsigned long long ull;

constexpr int B=128,S=256,T=256,V=512,E=256,H=512,G=2048,H2=1024,EH2=1280;
constexpr int NB=128, NT=256;

__device__ __align__(256) float g_xs[(size_t)2*S*B*E];
__device__ __align__(256) float g_edec[(size_t)T*B*E];
__device__ __align__(256) float g_pre[(size_t)2*S*B*G];
__device__ __align__(256) float g_y0[(size_t)2*S*B*H2];
__device__ __align__(256) __nv_bfloat16 g_encb[(size_t)S*B*H2];  // bf16 enc_out (attention only)
__device__ __align__(256) float g_hb[2][2*B*H];
__device__ __align__(256) float g_cst[2*B*H];
__device__ __align__(256) float g_q[B*H2];
__device__ __align__(256) float g_ctx[B*H2];
__device__ __align__(256) float g_d0hb[2][B*H];
__device__ __align__(256) float g_d1hb[2][B*H];
__device__ __align__(256) float g_h0i[B*H];
__device__ __align__(256) float g_c0i[B*H];
__device__ __align__(256) float g_h1i[B*H];
__device__ __align__(256) float g_c1i[B*H];
__device__ __align__(256) float g_gates[B*G];      // cell0 partner partial
// permuted weights (row g*H+j -> j*4+g) and permuted summed biases
__device__ __align__(256) float g_wE0ih[2*G*E];
__device__ __align__(256) float g_wE0hh[2*G*H];
__device__ __align__(256) float g_wE1ih[2*G*H2];
__device__ __align__(256) float g_wE1hh[2*G*H];
__device__ __align__(256) float g_wD0[G*EH2];
__device__ __align__(256) float g_wD0hh[G*H];
__device__ __align__(256) float g_wD1ih[G*H];
__device__ __align__(256) float g_wD1hh[G*H];
__device__ __align__(256) float g_be0[2*G];
__device__ __align__(256) float g_be1[2*G];
__device__ __align__(256) float g_bd0[G];
__device__ __align__(256) float g_bd1[G];

__device__ unsigned g_cnt, g_flag;

__device__ __forceinline__ void gbar(unsigned& phase)
{
    __syncthreads();
    if (threadIdx.x == 0) {
        __threadfence();
        const unsigned target = phase + 1;
        if (atomicAdd(&g_cnt, 1) == NB - 1) {
            g_cnt = 0; __threadfence();
            atomicExch(&g_flag, target);
        } else {
            while (*(volatile unsigned*)&g_flag < target) { __nanosleep(32); }
            __threadfence();
        }
        phase = target;
    }
    __syncthreads();
}

union UPair { ull u; float2 f; };
__device__ __forceinline__ ull dupf(float x){ ull r; asm("mov.b64 %0,{%1,%1};":"=l"(r):"f"(x)); return r; }
#define FMA2(d,a,b) asm("fma.rn.f32x2 %0,%1,%2,%0;":"+l"(d):"l"(a),"l"(b))
__device__ __forceinline__ float accf(ull a,int h){ UPair u; u.u=a; return h?u.f.y:u.f.x; }
__device__ __forceinline__ float sigf(float x){ return 1.f/(1.f+expf(-x)); }
__device__ __forceinline__ float2 bf2f(unsigned v){
    __nv_bfloat162 b=*reinterpret_cast<__nv_bfloat162*>(&v);
    return __bfloat1622float2(b);
}

// ---------------- 64x64 tile core, thread tile 2 rows x 8 cols ----------------
__device__ __forceinline__ void gcore3(const float* __restrict__ A,int lda,
    const float* __restrict__ W,int ldw,int K,
    float (*As)[66], float (*Bs)[68], ull acc[2][4])
{
    const int tid=threadIdx.x;
    const int tx=tid&7, ty=tid>>3;
    const int lr=tid>>2, lk=(tid&3)*4;
    const float* ap=A+(size_t)lr*lda+lk;
    const float* wp=W+(size_t)lr*ldw+lk;
    float4 pa=__ldcg((const float4*)ap);
    float4 pw=*(const float4*)wp;
    int buf=0;
    #pragma unroll 1
    for(int kk=0;kk<K;kk+=16){
        const int b16=buf<<4;
        As[b16+lk+0][lr]=pa.x; As[b16+lk+1][lr]=pa.y;
        As[b16+lk+2][lr]=pa.z; As[b16+lk+3][lr]=pa.w;
        Bs[b16+lk+0][lr]=pw.x; Bs[b16+lk+1][lr]=pw.y;
        Bs[b16+lk+2][lr]=pw.z; Bs[b16+lk+3][lr]=pw.w;
        __syncthreads();
        if(kk+16<K){ pa=__ldcg((const float4*)(ap+kk+16)); pw=*(const float4*)(wp+kk+16); }
        #pragma unroll
        for(int k=0;k<16;++k){
            const float2 a=*(const float2*)&As[b16+k][ty*2];
            const ull A0=dupf(a.x), A1=dupf(a.y);
            const ulonglong2 bL=*(const ulonglong2*)&Bs[b16+k][tx*4];
            const ulonglong2 bH=*(const ulonglong2*)&Bs[b16+k][32+tx*4];
            FMA2(acc[0][0],A0,bL.x); FMA2(acc[0][1],A0,bL.y);
            FMA2(acc[0][2],A0,bH.x); FMA2(acc[0][3],A0,bH.y);
            FMA2(acc[1][0],A1,bL.x); FMA2(acc[1][1],A1,bL.y);
            FMA2(acc[1][2],A1,bH.x); FMA2(acc[1][3],A1,bH.y);
        }
        buf^=1;
    }
}

// store with tile-relative bias (bias pre-offset by N-tile base, 64 wide)
__device__ __forceinline__ void store_out(ull acc[2][4], float* __restrict__ C,
                                          int ldc, const float* __restrict__ bias)
{
    const int tid=threadIdx.x, tx=tid&7, ty=tid>>3;
    const float4 bL=*(const float4*)(bias+tx*4);
    const float4 bH=*(const float4*)(bias+32+tx*4);
    #pragma unroll
    for(int r=0;r<2;++r){
        const int row=ty*2+r;
        float4 oL, oH;
        oL.x=accf(acc[r][0],0)+bL.x; oL.y=accf(acc[r][0],1)+bL.y;
        oL.z=accf(acc[r][1],0)+bL.z; oL.w=accf(acc[r][1],1)+bL.w;
        oH.x=accf(acc[r][2],0)+bH.x; oH.y=accf(acc[r][2],1)+bH.y;
        oH.z=accf(acc[r][3],0)+bH.z; oH.w=accf(acc[r][3],1)+bH.w;
        *(float4*)(C+(size_t)row*ldc+tx*4)=oL;
        *(float4*)(C+(size_t)row*ldc+32+tx*4)=oH;
    }
}

// raw partial store (no bias)
__device__ __forceinline__ void store_raw(ull acc[2][4], float* __restrict__ C, int ldc)
{
    const int tid=threadIdx.x, tx=tid&7, ty=tid>>3;
    #pragma unroll
    for(int r=0;r<2;++r){
        const int row=ty*2+r;
        float4 oL, oH;
        oL.x=accf(acc[r][0],0); oL.y=accf(acc[r][0],1);
        oL.z=accf(acc[r][1],0); oL.w=accf(acc[r][1],1);
        oH.x=accf(acc[r][2],0); oH.y=accf(acc[r][2],1);
        oH.z=accf(acc[r][3],0); oH.w=accf(acc[r][3],1);
        *(float4*)(C+(size_t)row*ldc+tx*4)=oL;
        *(float4*)(C+(size_t)row*ldc+32+tx*4)=oH;
    }
}

// ---------------- prep: embeddings + weight permutation + bias sums ----------------
__global__ void prep_k(const int* __restrict__ src,const int* __restrict__ dec,
    const float* __restrict__ emb,
    const float* eWih0,const float* eWhh0,const float* ebih0,const float* ebhh0,
    const float* eWih1,const float* eWhh1,const float* ebih1,const float* ebhh1,
    const float* dWih0,const float* dWhh0,const float* dbih0,const float* dbhh0,
    const float* dWih1,const float* dWhh1,const float* dbih1,const float* dbhh1)
{
    const int id=blockIdx.x*blockDim.x+threadIdx.x;
    const int stride=gridDim.x*blockDim.x;
    for(int i=id;i<S*B*E;i+=stride){
        const int j=i%E, b=(i/E)%B, t=i/(E*B);
        const int tok=src[b*S+t];
        const float v=tok?emb[(size_t)tok*E+j]:0.f;
        g_xs[((size_t)t*B+b)*E+j]=v;
        g_xs[(size_t)S*B*E+((size_t)(S-1-t)*B+b)*E+j]=v;
    }
    for(int i=id;i<T*B*E;i+=stride){
        const int j=i%E, b=(i/E)%B, t=i/(E*B);
        const int tok=dec[b*T+t];
        g_edec[((size_t)t*B+b)*E+j]=tok?emb[(size_t)tok*E+j]:0.f;
    }
    auto P=[&](float* dst,const float* s2,int WID,int ZG){
        const int tot=ZG*G*WID;
        for(int i=id;i<tot;i+=stride){
            const int z=i/(G*WID), r=i-z*(G*WID), p=r/WID, k=r-p*WID;
            dst[i]=s2[((size_t)z*G+(p&3)*H+(p>>2))*WID+k];
        }
    };
    P(g_wE0ih,eWih0,E,2);  P(g_wE0hh,eWhh0,H,2);
    P(g_wE1ih,eWih1,H2,2); P(g_wE1hh,eWhh1,H,2);
    P(g_wD0,dWih0,EH2,1);  P(g_wD0hh,dWhh0,H,1);
    P(g_wD1ih,dWih1,H,1);  P(g_wD1hh,dWhh1,H,1);
    auto PB=[&](float* dst,const float* b0,const float* b1,int ZG){
        for(int i=id;i<ZG*G;i+=stride){
            const int z=i/G, p=i-z*G, o=(p&3)*H+(p>>2);
            dst[i]=b0[z*G+o]+b1[z*G+o];
        }
    };
    PB(g_be0,ebih0,ebhh0,2); PB(g_be1,ebih1,ebhh1,2);
    PB(g_bd0,dbih0,dbhh0,1); PB(g_bd1,dbih1,dbhh1,1);
}

// ---------------- precompute GEMM ----------------
__global__ __launch_bounds__(256,4) void gemm2_k(
    const float* __restrict__ A,int lda,int K,
    const float* __restrict__ W,int ldw,
    const float* __restrict__ bias,float* __restrict__ C,int ldc,
    long long zsA,long long zsW,long long zsB,long long zsC)
{
    __shared__ __align__(16) float As[32][66];
    __shared__ __align__(16) float Bs[32][68];
    const int z=blockIdx.z;
    ull acc[2][4]={{0,0,0,0},{0,0,0,0}};
    gcore3(A+z*zsA+(size_t)blockIdx.y*64*lda, lda,
           W+z*zsW+(size_t)blockIdx.x*64*ldw, ldw, K, As,Bs,acc);
    store_out(acc, C+z*zsC+(size_t)blockIdx.y*64*ldc+blockIdx.x*64, ldc,
              bias+z*zsB+blockIdx.x*64);
}

// ---------------- persistent encoder layer: fused pointwise, c in regs ----------------
__global__ __launch_bounds__(NT,1) void enc_layer_k(
    const float* __restrict__ pre, const float* __restrict__ whp,
    float* __restrict__ ynorm, float* __restrict__ yrev,
    __nv_bfloat16* __restrict__ encb,
    float* __restrict__ hsum, float* __restrict__ csum)
{
    __shared__ __align__(16) float As[32][66];
    __shared__ __align__(16) float Bs[32][68];
    const int cta=blockIdx.x, tid=threadIdx.x;
    unsigned ph=*(volatile unsigned*)&g_flag;
    for(int i=cta*NT+tid;i<2*B*H;i+=NB*NT) g_hb[0][i]=0.f;
    gbar(ph);
    const int dir=cta>>6, rr=cta&63, mt=rr>>5, nt=rr&31;
    const int tx=tid&7, ty=tid>>3;
    const float* Wt=whp+((size_t)dir*G+(size_t)nt*64)*H;
    float c[2][2]={{0.f,0.f},{0.f,0.f}};
    #pragma unroll 1
    for(int s=0;s<S;++s){
        const int par=s&1;
        ull acc[2][4]={{0,0,0,0},{0,0,0,0}};
        gcore3(g_hb[par]+(size_t)dir*B*H+(size_t)mt*64*H, H, Wt, H, H, As,Bs,acc);
        const float* preT=pre+(((size_t)dir*S+s)*B+mt*64)*G+nt*64;
        float* hout=g_hb[par^1]+(size_t)dir*B*H;
        const int tt=dir?(S-1-s):s;
        #pragma unroll
        for(int r=0;r<2;++r){
            const int row=ty*2+r;
            const int b=mt*64+row;
            #pragma unroll
            for(int h=0;h<2;++h){
                const float4 pv=__ldcg((const float4*)(preT+(size_t)row*G+h*32+tx*4));
                const float gi=accf(acc[r][2*h+0],0)+pv.x;
                const float gf=accf(acc[r][2*h+0],1)+pv.y;
                const float gg=accf(acc[r][2*h+1],0)+pv.z;
                const float go=accf(acc[r][2*h+1],1)+pv.w;
                const float cn=sigf(gf)*c[r][h]+sigf(gi)*tanhf(gg);
                c[r][h]=cn;
                const float hn=sigf(go)*tanhf(cn);
                const int u=nt*16+h*8+tx;
                hout[(size_t)b*H+u]=hn;
                if(ynorm) ynorm[((size_t)tt*B+b)*H2+dir*H+u]=hn;
                if(yrev)  yrev[((size_t)(S-1-tt)*B+b)*H2+dir*H+u]=hn;
                if(encb)  encb[((size_t)tt*B+b)*H2+dir*H+u]=__float2bfloat16(hn);
            }
        }
        gbar(ph);
    }
    #pragma unroll
    for(int r=0;r<2;++r)
        #pragma unroll
        for(int h=0;h<2;++h)
            g_cst[(size_t)dir*B*H+(size_t)(mt*64+ty*2+r)*H+nt*16+h*8+tx]=c[r][h];
    gbar(ph);
    for(int i=cta*NT+tid;i<B*H;i+=NB*NT){
        hsum[i]=__ldcg(&g_hb[0][i])+__ldcg(&g_hb[0][B*H+i]);
        csum[i]=__ldcg(&g_cst[i])+__ldcg(&g_cst[B*H+i]);
    }
}

// ---------------- persistent decoder ----------------
__global__ __launch_bounds__(NT,1) void dec_k(
    const float* __restrict__ pre, const int* __restrict__ src,
    const __nv_bfloat16* __restrict__ enc,
    const float* __restrict__ Wq, const float* __restrict__ bq,
    const float* __restrict__ Wout, const float* __restrict__ bout,
    float* __restrict__ out)
{
    __shared__ __align__(16) float As[32][66];
    __shared__ __align__(16) float Bs[32][68];
    __shared__ float qs[H2];
    __shared__ float sc[S];
    __shared__ float red[8];
    __shared__ float s_max, s_sum;
    const int cta=blockIdx.x, tid=threadIdx.x, lane=tid&31, w=tid>>5;
    const int tx=tid&7, ty=tid>>3;
    unsigned ph=*(volatile unsigned*)&g_flag;

    for(int i=cta*NT+tid;i<B*H;i+=NB*NT){
        g_d0hb[1][i]=g_h0i[i];
        g_d1hb[1][i]=g_h1i[i];
    }
    // cell-state registers: cta<64 owns c0 tile (mt=cta>>5,nt=cta&31),
    // cta>=64 owns c1 tile (cc=cta-64).
    float c[2][2];
    {
        const int cc=cta&63, mt=cc>>5, nt=cc&31;
        const float* cs=(cta<64)?g_c0i:g_c1i;
        #pragma unroll
        for(int r=0;r<2;++r)
            #pragma unroll
            for(int h=0;h<2;++h)
                c[r][h]=cs[(size_t)(mt*64+ty*2+r)*H+nt*16+h*8+tx];
    }
    gbar(ph);

    #pragma unroll 1
    for(int t=0;t<T;++t){
        const int par=t&1;
        const float* h1p=g_d1hb[par^1];
        ull accW[2][4]={{0,0,0,0},{0,0,0,0}};   // whh1 partial, lives in regs until P5

        // ---- P1: q (0..31) | logits t-1 (32..47) | whh1*d1h_prev (64..127, regs)
        if(cta<32){
            const int mt=cta>>4, nt=cta&15;
            ull acc[2][4]={{0,0,0,0},{0,0,0,0}};
            gcore3(h1p+(size_t)mt*64*H, H, Wq+(size_t)nt*64*H, H, H, As,Bs,acc);
            store_out(acc, g_q+(size_t)mt*64*H2+nt*64, H2, bq+nt*64);
        } else if(cta<48){
            if(t>0){
                const int ct=cta-32, mt=ct>>3, nt=ct&7;
                ull acc[2][4]={{0,0,0,0},{0,0,0,0}};
                gcore3(h1p+(size_t)mt*64*H, H, Wout+(size_t)nt*64*H, H, H, As,Bs,acc);
                store_out(acc, out+(size_t)mt*64*(T*V)+(size_t)(t-1)*V+nt*64, T*V, bout+nt*64);
            }
        } else if(cta>=64){
            const int cc=cta-64, mt=cc>>5, nt=cc&31;
            gcore3(h1p+(size_t)mt*64*H, H, g_wD1hh+(size_t)nt*64*H, H, H, As,Bs,accW);
        }
        gbar(ph);

        // ---- P2: attention (CTA = batch), bf16 enc
        {
            const int b=cta;
            for(int k=tid*4;k<H2;k+=NT*4)
                *(float4*)&qs[k]=__ldcg((const float4*)(g_q+(size_t)b*H2+k));
            __syncthreads();
            for(int s=w;s<S;s+=8){
                const __nv_bfloat16* eb=enc+((size_t)s*B+b)*H2;
                float sum=0.f;
                #pragma unroll
                for(int k=lane*8;k<H2;k+=256){
                    const uint4 ev=*(const uint4*)(eb+k);
                    const float2 f0=bf2f(ev.x), f1=bf2f(ev.y);
                    const float2 f2=bf2f(ev.z), f3=bf2f(ev.w);
                    sum+=f0.x*qs[k]+f0.y*qs[k+1]+f1.x*qs[k+2]+f1.y*qs[k+3]
                        +f2.x*qs[k+4]+f2.y*qs[k+5]+f3.x*qs[k+6]+f3.y*qs[k+7];
                }
                #pragma unroll
                for(int o=16;o;o>>=1) sum+=__shfl_xor_sync(0xffffffffu,sum,o);
                if(lane==0) sc[s]=(src[b*S+s]!=0)?sum:-1e9f;
            }
            __syncthreads();
            const float v=sc[tid];
            float m=v;
            #pragma unroll
            for(int o=16;o;o>>=1) m=fmaxf(m,__shfl_xor_sync(0xffffffffu,m,o));
            if(lane==0) red[w]=m;
            __syncthreads();
            if(tid==0){
                float mm=red[0];
                #pragma unroll
                for(int i=1;i<8;++i) mm=fmaxf(mm,red[i]);
                s_max=mm;
            }
            __syncthreads();
            const float ev=expf(v-s_max);
            float sum=ev;
            #pragma unroll
            for(int o=16;o;o>>=1) sum+=__shfl_xor_sync(0xffffffffu,sum,o);
            if(lane==0) red[w]=sum;
            __syncthreads();
            if(tid==0){
                float ss=0.f;
                #pragma unroll
                for(int i=0;i<8;++i) ss+=red[i];
                s_sum=ss;
            }
            __syncthreads();
            sc[tid]=ev/s_sum;
            __syncthreads();
            const int k4=tid*4;
            float4 a={0.f,0.f,0.f,0.f};
            const __nv_bfloat16* ep=enc+(size_t)b*H2+k4;
            #pragma unroll 8
            for(int s=0;s<S;++s){
                const float p=sc[s];
                const uint2 ev2=*(const uint2*)(ep+(size_t)s*B*H2);
                const float2 f0=bf2f(ev2.x), f1=bf2f(ev2.y);
                a.x+=p*f0.x; a.y+=p*f0.y; a.z+=p*f1.x; a.w+=p*f1.y;
            }
            *(float4*)(g_ctx+(size_t)b*H2+k4)=a;
        }
        gbar(ph);

        // ---- P3: cell0 K-split. Owner (0..63): ctx[0:768]*Wc, regs.
        //      Partner (64..127): ctx[768:1024]*Wc + d0h_prev*whh0 -> g_gates.
        ull acc[2][4]={{0,0,0,0},{0,0,0,0}};
        if(cta<64){
            const int mt=cta>>5, nt=cta&31;
            gcore3(g_ctx+(size_t)mt*64*H2, H2, g_wD0+E+(size_t)nt*64*EH2, EH2, 768, As,Bs,acc);
        } else {
            const int cc=cta-64, mt=cc>>5, nt=cc&31;
            gcore3(g_ctx+(size_t)mt*64*H2+768, H2, g_wD0+E+768+(size_t)nt*64*EH2, EH2, 256, As,Bs,acc);
            gcore3(g_d0hb[par^1]+(size_t)mt*64*H, H, g_wD0hh+(size_t)nt*64*H, H, H, As,Bs,acc);
            store_raw(acc, g_gates+(size_t)(mt*64)*G+nt*64, G);
        }
        gbar(ph);

        // ---- P4: cell0 epilogue (owner combines reg acc + partner partial + pre)
        if(cta<64){
            const int mt=cta>>5, nt=cta&31;
            const float* preT=pre+((size_t)t*B+mt*64)*G+nt*64;
            const float* parT=g_gates+(size_t)(mt*64)*G+nt*64;
            float* hout=g_d0hb[par];
            #pragma unroll
            for(int r=0;r<2;++r){
                const int row=ty*2+r;
                const int b=mt*64+row;
                #pragma unroll
                for(int h=0;h<2;++h){
                    const float4 pv=__ldcg((const float4*)(preT+(size_t)row*G+h*32+tx*4));
                    const float4 gv=__ldcg((const float4*)(parT+(size_t)row*G+h*32+tx*4));
                    const float gi=accf(acc[r][2*h+0],0)+pv.x+gv.x;
                    const float gf=accf(acc[r][2*h+0],1)+pv.y+gv.y;
                    const float gg=accf(acc[r][2*h+1],0)+pv.z+gv.z;
                    const float go=accf(acc[r][2*h+1],1)+pv.w+gv.w;
                    const float cn=sigf(gf)*c[r][h]+sigf(gi)*tanhf(gg);
                    c[r][h]=cn;
                    hout[(size_t)b*H+nt*16+h*8+tx]=sigf(go)*tanhf(cn);
                }
            }
        }
        gbar(ph);

        // ---- P5: cell1 (owner 64..127): wih1*d0h_t into accW, fused epilogue
        if(cta>=64){
            const int cc=cta-64, mt=cc>>5, nt=cc&31;
            gcore3(g_d0hb[par]+(size_t)mt*64*H, H, g_wD1ih+(size_t)nt*64*H, H, H, As,Bs,accW);
            float* hout=g_d1hb[par];
            const float4 bL=*(const float4*)(g_bd1+nt*64+tx*4);
            const float4 bH=*(const float4*)(g_bd1+nt*64+32+tx*4);
            #pragma unroll
            for(int r=0;r<2;++r){
                const int b=mt*64+ty*2+r;
                #pragma unroll
                for(int h=0;h<2;++h){
                    const float4 bv=h?bH:bL;
                    const float gi=accf(accW[r][2*h+0],0)+bv.x;
                    const float gf=accf(accW[r][2*h+0],1)+bv.y;
                    const float gg=accf(accW[r][2*h+1],0)+bv.z;
                    const float go=accf(accW[r][2*h+1],1)+bv.w;
                    const float cn=sigf(gf)*c[r][h]+sigf(gi)*tanhf(gg);
                    c[r][h]=cn;
                    hout[(size_t)b*H+nt*16+h*8+tx]=sigf(go)*tanhf(cn);
                }
            }
        }
        gbar(ph);
    }
    // final logits (t = T-1); last d1h written to parity (T-1)&1 = 1
    if(cta>=32&&cta<48){
        const int ct=cta-32, mt=ct>>3, nt=ct&7;
        ull acc[2][4]={{0,0,0,0},{0,0,0,0}};
        gcore3(g_d1hb[1]+(size_t)mt*64*H, H, Wout+(size_t)nt*64*H, H, H, As,Bs,acc);
        store_out(acc, out+(size_t)mt*64*(T*V)+(size_t)(T-1)*V+nt*64, T*V, bout+nt*64);
    }
}

// ---------------- host ----------------
static inline void* sym(const void* s){ void* p=nullptr; cudaGetSymbolAddress(&p,s); return p; }

extern "C" void kernel_launch(void* const* d_in, const int* in_sizes, int n_in,
                              void* d_out, int out_size)
{
    (void)in_sizes;(void)n_in;(void)out_size;
    const int* src=(const int*)d_in[0];
    const int* decin=(const int*)d_in[1];
    const float* emb=(const float*)d_in[2];
    const float* eWih0=(const float*)d_in[3];
    const float* eWhh0=(const float*)d_in[4];
    const float* ebih0=(const float*)d_in[5];
    const float* ebhh0=(const float*)d_in[6];
    const float* eWih1=(const float*)d_in[7];
    const float* eWhh1=(const float*)d_in[8];
    const float* ebih1=(const float*)d_in[9];
    const float* ebhh1=(const float*)d_in[10];
    const float* dWih0=(const float*)d_in[11];
    const float* dWhh0=(const float*)d_in[12];
    const float* dbih0=(const float*)d_in[13];
    const float* dbhh0=(const float*)d_in[14];
    const float* dWih1=(const float*)d_in[15];
    const float* dWhh1=(const float*)d_in[16];
    const float* dbih1=(const float*)d_in[17];
    const float* dbhh1=(const float*)d_in[18];
    const float* Wq=(const float*)d_in[19];
    const float* bq=(const float*)d_in[20];
    const float* Wout=(const float*)d_in[21];
    const float* bout=(const float*)d_in[22];
    float* out=(float*)d_out;

    float* xs=(float*)sym(g_xs);    float* pre=(float*)sym(g_pre);
    float* y0=(float*)sym(g_y0);
    __nv_bfloat16* encb=(__nv_bfloat16*)sym(g_encb);
    float* edec=(float*)sym(g_edec);
    float* wE0ih=(float*)sym(g_wE0ih); float* wE0hh=(float*)sym(g_wE0hh);
    float* wE1ih=(float*)sym(g_wE1ih); float* wE1hh=(float*)sym(g_wE1hh);
    float* wD0=(float*)sym(g_wD0);
    float* be0=(float*)sym(g_be0);  float* be1=(float*)sym(g_be1);
    float* bd0=(float*)sym(g_bd0);
    float* h0i=(float*)sym(g_h0i);  float* c0i=(float*)sym(g_c0i);
    float* h1i=(float*)sym(g_h1i);  float* c1i=(float*)sym(g_c1i);

    prep_k<<<512,NT>>>(src,decin,emb,
        eWih0,eWhh0,ebih0,ebhh0, eWih1,eWhh1,ebih1,ebhh1,
        dWih0,dWhh0,dbih0,dbhh0, dWih1,dWhh1,dbih1,dbhh1);

    const long long SBG=(long long)S*B*G;
    // encoder layer0 input projections
    gemm2_k<<<dim3(32,(S*B)/64,2),256>>>(xs,E,E, wE0ih,E, be0, pre,G,
        (long long)S*B*E,(long long)G*E,G,SBG);
    enc_layer_k<<<NB,NT>>>(pre, wE0hh, y0, y0+(size_t)S*B*H2, nullptr, h0i,c0i);
    // encoder layer1 input projections
    gemm2_k<<<dim3(32,(S*B)/64,2),256>>>(y0,H2,H2, wE1ih,H2, be1, pre,G,
        (long long)S*B*H2,(long long)G*H2,G,SBG);
    enc_layer_k<<<NB,NT>>>(pre, wE1hh, nullptr, nullptr, encb, h1i,c1i);
    // decoder embedding projection (emb cols of dWih0, biases folded)
    gemm2_k<<<dim3(32,(T*B)/64,1),256>>>(edec,E,E, wD0,EH2, bd0, pre,G, 0,0,0,0);
    // decoder
    dec_k<<<NB,NT>>>(pre, src, encb, Wq,bq, Wout,bout, out);
}

// round 12
// speedup vs baseline: 2.6999x; 1.1786x over previous
#include <cuda_runtime.h>
#include <cuda_bf16.h>
#include <math.h>
typedef unsigned long long ull;

constexpr int B=128,S=256,T=256,V=512,E=256,H=512,G=2048,H2=1024,EH2=1280;
constexpr int NB=128, NT=256;

__device__ __align__(256) float g_xs[(size_t)2*S*B*E];
__device__ __align__(256) float g_edec[(size_t)T*B*E];
__device__ __align__(256) float g_pre[(size_t)2*S*B*G];
__device__ __align__(256) float g_preD[(size_t)T*B*G];
__device__ __align__(256) float g_y0[(size_t)2*S*B*H2];
__device__ __align__(256) __nv_bfloat16 g_encb[(size_t)S*B*H2];  // bf16 enc_out (attention only)
__device__ __align__(256) float g_hb[2][2*B*H];
__device__ __align__(256) float g_cst[2*B*H];
__device__ __align__(256) float g_q[B*H2];
__device__ __align__(256) float g_ctx[B*H2];
__device__ __align__(256) float g_d0hb[2][B*H];
__device__ __align__(256) float g_d1hb[2][B*H];
__device__ __align__(256) float g_h0i[B*H];
__device__ __align__(256) float g_c0i[B*H];
__device__ __align__(256) float g_h1i[B*H];
__device__ __align__(256) float g_c1i[B*H];
__device__ __align__(256) float g_gates[B*G];      // cell0 partner partial
// permuted weights (row g*H+j -> j*4+g) and permuted summed biases
__device__ __align__(256) float g_wE0ih[2*G*E];
__device__ __align__(256) float g_wE0hh[2*G*H];
__device__ __align__(256) float g_wE1ih[2*G*H2];
__device__ __align__(256) float g_wE1hh[2*G*H];
__device__ __align__(256) float g_wD0[G*EH2];
__device__ __align__(256) float g_wD0hh[G*H];
__device__ __align__(256) float g_wD1ih[G*H];
__device__ __align__(256) float g_wD1hh[G*H];
__device__ __align__(256) float g_be0[2*G];
__device__ __align__(256) float g_be1[2*G];
__device__ __align__(256) float g_bd0[G];
__device__ __align__(256) float g_bd1[G];

__device__ unsigned g_cnt, g_flag;

__device__ __forceinline__ void gbar(unsigned& phase)
{
    __syncthreads();
    if (threadIdx.x == 0) {
        __threadfence();
        const unsigned target = phase + 1;
        if (atomicAdd(&g_cnt, 1) == NB - 1) {
            g_cnt = 0; __threadfence();
            atomicExch(&g_flag, target);
        } else {
            while (*(volatile unsigned*)&g_flag < target) { __nanosleep(32); }
            __threadfence();
        }
        phase = target;
    }
    __syncthreads();
}

union UPair { ull u; float2 f; };
__device__ __forceinline__ ull dupf(float x){ ull r; asm("mov.b64 %0,{%1,%1};":"=l"(r):"f"(x)); return r; }
#define FMA2(d,a,b) asm("fma.rn.f32x2 %0,%1,%2,%0;":"+l"(d):"l"(a),"l"(b))
__device__ __forceinline__ float accf(ull a,int h){ UPair u; u.u=a; return h?u.f.y:u.f.x; }
__device__ __forceinline__ float sigf(float x){ return 1.f/(1.f+expf(-x)); }
__device__ __forceinline__ float2 bf2f(unsigned v){
    __nv_bfloat162 b=*reinterpret_cast<__nv_bfloat162*>(&v);
    return __bfloat1622float2(b);
}

// ---------------- 64x64 tile core, thread tile 4 rows x 4 cols ----------------
// tx=tid&15 -> col group tx*4..+3 (one permuted gate unit); ty=tid>>4 -> rows ty*4..+3.
// acc[r][0] = cols (tx*4, tx*4+1) = (i,f); acc[r][1] = (g,o). 32B smem per 32 FLOP.
__device__ __forceinline__ void gcore4(const float* __restrict__ A,int lda,
    const float* __restrict__ W,int ldw,int K,
    float (*As)[68], float (*Bs)[68], ull acc[4][2])
{
    const int tid=threadIdx.x;
    const int tx=tid&15, ty=tid>>4;
    const int lr=tid>>2, lk=(tid&3)*4;
    const float* ap=A+(size_t)lr*lda+lk;
    const float* wp=W+(size_t)lr*ldw+lk;
    float4 pa=__ldcg((const float4*)ap);
    float4 pw=*(const float4*)wp;
    int buf=0;
    #pragma unroll 1
    for(int kk=0;kk<K;kk+=16){
        const int b16=buf<<4;
        As[b16+lk+0][lr]=pa.x; As[b16+lk+1][lr]=pa.y;
        As[b16+lk+2][lr]=pa.z; As[b16+lk+3][lr]=pa.w;
        Bs[b16+lk+0][lr]=pw.x; Bs[b16+lk+1][lr]=pw.y;
        Bs[b16+lk+2][lr]=pw.z; Bs[b16+lk+3][lr]=pw.w;
        __syncthreads();
        if(kk+16<K){ pa=__ldcg((const float4*)(ap+kk+16)); pw=*(const float4*)(wp+kk+16); }
        #pragma unroll
        for(int k=0;k<16;++k){
            const float4 a=*(const float4*)&As[b16+k][ty*4];
            const ull A0=dupf(a.x), A1=dupf(a.y), A2=dupf(a.z), A3=dupf(a.w);
            const ulonglong2 bv=*(const ulonglong2*)&Bs[b16+k][tx*4];
            FMA2(acc[0][0],A0,bv.x); FMA2(acc[0][1],A0,bv.y);
            FMA2(acc[1][0],A1,bv.x); FMA2(acc[1][1],A1,bv.y);
            FMA2(acc[2][0],A2,bv.x); FMA2(acc[2][1],A2,bv.y);
            FMA2(acc[3][0],A3,bv.x); FMA2(acc[3][1],A3,bv.y);
        }
        buf^=1;
    }
}

// store with tile-relative bias (bias pre-offset by N-tile base, 64 wide)
__device__ __forceinline__ void store_out(ull acc[4][2], float* __restrict__ C,
                                          int ldc, const float* __restrict__ bias)
{
    const int tid=threadIdx.x, tx=tid&15, ty=tid>>4;
    const float4 bv=*(const float4*)(bias+tx*4);
    #pragma unroll
    for(int r=0;r<4;++r){
        const int row=ty*4+r;
        float4 o;
        o.x=accf(acc[r][0],0)+bv.x; o.y=accf(acc[r][0],1)+bv.y;
        o.z=accf(acc[r][1],0)+bv.z; o.w=accf(acc[r][1],1)+bv.w;
        *(float4*)(C+(size_t)row*ldc+tx*4)=o;
    }
}

// raw partial store (no bias)
__device__ __forceinline__ void store_raw(ull acc[4][2], float* __restrict__ C, int ldc)
{
    const int tid=threadIdx.x, tx=tid&15, ty=tid>>4;
    #pragma unroll
    for(int r=0;r<4;++r){
        const int row=ty*4+r;
        float4 o;
        o.x=accf(acc[r][0],0); o.y=accf(acc[r][0],1);
        o.z=accf(acc[r][1],0); o.w=accf(acc[r][1],1);
        *(float4*)(C+(size_t)row*ldc+tx*4)=o;
    }
}

// ---------------- prep: embeddings + weight permutation + bias sums ----------------
__global__ void prep_k(const int* __restrict__ src,const int* __restrict__ dec,
    const float* __restrict__ emb,
    const float* eWih0,const float* eWhh0,const float* ebih0,const float* ebhh0,
    const float* eWih1,const float* eWhh1,const float* ebih1,const float* ebhh1,
    const float* dWih0,const float* dWhh0,const float* dbih0,const float* dbhh0,
    const float* dWih1,const float* dWhh1,const float* dbih1,const float* dbhh1)
{
    const int id=blockIdx.x*blockDim.x+threadIdx.x;
    const int stride=gridDim.x*blockDim.x;
    for(int i=id;i<S*B*E;i+=stride){
        const int j=i%E, b=(i/E)%B, t=i/(E*B);
        const int tok=src[b*S+t];
        const float v=tok?emb[(size_t)tok*E+j]:0.f;
        g_xs[((size_t)t*B+b)*E+j]=v;
        g_xs[(size_t)S*B*E+((size_t)(S-1-t)*B+b)*E+j]=v;
    }
    for(int i=id;i<T*B*E;i+=stride){
        const int j=i%E, b=(i/E)%B, t=i/(E*B);
        const int tok=dec[b*T+t];
        g_edec[((size_t)t*B+b)*E+j]=tok?emb[(size_t)tok*E+j]:0.f;
    }
    auto P=[&](float* dst,const float* s2,int WID,int ZG){
        const int tot=ZG*G*WID;
        for(int i=id;i<tot;i+=stride){
            const int z=i/(G*WID), r=i-z*(G*WID), p=r/WID, k=r-p*WID;
            dst[i]=s2[((size_t)z*G+(p&3)*H+(p>>2))*WID+k];
        }
    };
    P(g_wE0ih,eWih0,E,2);  P(g_wE0hh,eWhh0,H,2);
    P(g_wE1ih,eWih1,H2,2); P(g_wE1hh,eWhh1,H,2);
    P(g_wD0,dWih0,EH2,1);  P(g_wD0hh,dWhh0,H,1);
    P(g_wD1ih,dWih1,H,1);  P(g_wD1hh,dWhh1,H,1);
    auto PB=[&](float* dst,const float* b0,const float* b1,int ZG){
        for(int i=id;i<ZG*G;i+=stride){
            const int z=i/G, p=i-z*G, o=(p&3)*H+(p>>2);
            dst[i]=b0[z*G+o]+b1[z*G+o];
        }
    };
    PB(g_be0,ebih0,ebhh0,2); PB(g_be1,ebih1,ebhh1,2);
    PB(g_bd0,dbih0,dbhh0,1); PB(g_bd1,dbih1,dbhh1,1);
}

// ---------------- precompute GEMM ----------------
__global__ __launch_bounds__(256,4) void gemm2_k(
    const float* __restrict__ A,int lda,int K,
    const float* __restrict__ W,int ldw,
    const float* __restrict__ bias,float* __restrict__ C,int ldc,
    long long zsA,long long zsW,long long zsB,long long zsC)
{
    __shared__ __align__(16) float As[32][68];
    __shared__ __align__(16) float Bs[32][68];
    const int z=blockIdx.z;
    ull acc[4][2]={{0,0},{0,0},{0,0},{0,0}};
    gcore4(A+z*zsA+(size_t)blockIdx.y*64*lda, lda,
           W+z*zsW+(size_t)blockIdx.x*64*ldw, ldw, K, As,Bs,acc);
    store_out(acc, C+z*zsC+(size_t)blockIdx.y*64*ldc+blockIdx.x*64, ldc,
              bias+z*zsB+blockIdx.x*64);
}

// ---------------- persistent encoder layer: fused pointwise, c in regs ----------------
__global__ __launch_bounds__(NT,1) void enc_layer_k(
    const float* __restrict__ pre, const float* __restrict__ whp,
    float* __restrict__ ynorm, float* __restrict__ yrev,
    __nv_bfloat16* __restrict__ encb,
    float* __restrict__ hsum, float* __restrict__ csum)
{
    __shared__ __align__(16) float As[32][68];
    __shared__ __align__(16) float Bs[32][68];
    const int cta=blockIdx.x, tid=threadIdx.x;
    unsigned ph=*(volatile unsigned*)&g_flag;
    for(int i=cta*NT+tid;i<2*B*H;i+=NB*NT) g_hb[0][i]=0.f;
    gbar(ph);
    const int dir=cta>>6, rr=cta&63, mt=rr>>5, nt=rr&31;
    const int tx=tid&15, ty=tid>>4;
    const int u=nt*16+tx;
    const float* Wt=whp+((size_t)dir*G+(size_t)nt*64)*H;
    float c[4]={0.f,0.f,0.f,0.f};
    #pragma unroll 1
    for(int s=0;s<S;++s){
        const int par=s&1;
        ull acc[4][2]={{0,0},{0,0},{0,0},{0,0}};
        gcore4(g_hb[par]+(size_t)dir*B*H+(size_t)mt*64*H, H, Wt, H, H, As,Bs,acc);
        const float* preT=pre+(((size_t)dir*S+s)*B+mt*64)*G+nt*64;
        float* hout=g_hb[par^1]+(size_t)dir*B*H;
        const int tt=dir?(S-1-s):s;
        #pragma unroll
        for(int r=0;r<4;++r){
            const int row=ty*4+r;
            const int b=mt*64+row;
            const float4 pv=__ldcg((const float4*)(preT+(size_t)row*G+tx*4));
            const float gi=accf(acc[r][0],0)+pv.x;
            const float gf=accf(acc[r][0],1)+pv.y;
            const float gg=accf(acc[r][1],0)+pv.z;
            const float go=accf(acc[r][1],1)+pv.w;
            const float cn=sigf(gf)*c[r]+sigf(gi)*tanhf(gg);
            c[r]=cn;
            const float hn=sigf(go)*tanhf(cn);
            hout[(size_t)b*H+u]=hn;
            if(ynorm) ynorm[((size_t)tt*B+b)*H2+dir*H+u]=hn;
            if(yrev)  yrev[((size_t)(S-1-tt)*B+b)*H2+dir*H+u]=hn;
            if(encb)  encb[((size_t)tt*B+b)*H2+dir*H+u]=__float2bfloat16(hn);
        }
        gbar(ph);
    }
    #pragma unroll
    for(int r=0;r<4;++r)
        g_cst[(size_t)dir*B*H+(size_t)(mt*64+ty*4+r)*H+u]=c[r];
    gbar(ph);
    for(int i=cta*NT+tid;i<B*H;i+=NB*NT){
        hsum[i]=__ldcg(&g_hb[0][i])+__ldcg(&g_hb[0][B*H+i]);
        csum[i]=__ldcg(&g_cst[i])+__ldcg(&g_cst[B*H+i]);
    }
}

// ---------------- persistent decoder ----------------
__global__ __launch_bounds__(NT,1) void dec_k(
    const float* __restrict__ pre, const int* __restrict__ src,
    const __nv_bfloat16* __restrict__ enc,
    const float* __restrict__ Wq, const float* __restrict__ bq,
    const float* __restrict__ Wout, const float* __restrict__ bout,
    float* __restrict__ out)
{
    __shared__ __align__(16) float As[32][68];
    __shared__ __align__(16) float Bs[32][68];
    __shared__ float qs[H2];
    __shared__ float sc[S];
    __shared__ float red[8];
    __shared__ float s_max, s_sum;
    const int cta=blockIdx.x, tid=threadIdx.x, lane=tid&31, w=tid>>5;
    const int tx=tid&15, ty=tid>>4;
    unsigned ph=*(volatile unsigned*)&g_flag;

    for(int i=cta*NT+tid;i<B*H;i+=NB*NT){
        g_d0hb[1][i]=g_h0i[i];
        g_d1hb[1][i]=g_h1i[i];
    }
    // cell-state registers: cta<64 owns c0 tile, cta>=64 owns c1 tile (cc=cta-64).
    float c[4];
    {
        const int cc=cta&63, mt=cc>>5, nt=cc&31;
        const float* cs=(cta<64)?g_c0i:g_c1i;
        #pragma unroll
        for(int r=0;r<4;++r)
            c[r]=cs[(size_t)(mt*64+ty*4+r)*H+nt*16+tx];
    }
    gbar(ph);

    #pragma unroll 1
    for(int t=0;t<T;++t){
        const int par=t&1;
        const float* h1p=g_d1hb[par^1];
        ull accW[4][2]={{0,0},{0,0},{0,0},{0,0}};   // whh1 partial, regs until P5

        // ---- P1: q (0..31) | logits t-1 (32..47) | whh1*d1h_prev (64..127, regs)
        if(cta<32){
            const int mt=cta>>4, nt=cta&15;
            ull acc[4][2]={{0,0},{0,0},{0,0},{0,0}};
            gcore4(h1p+(size_t)mt*64*H, H, Wq+(size_t)nt*64*H, H, H, As,Bs,acc);
            store_out(acc, g_q+(size_t)mt*64*H2+nt*64, H2, bq+nt*64);
        } else if(cta<48){
            if(t>0){
                const int ct=cta-32, mt=ct>>3, nt=ct&7;
                ull acc[4][2]={{0,0},{0,0},{0,0},{0,0}};
                gcore4(h1p+(size_t)mt*64*H, H, Wout+(size_t)nt*64*H, H, H, As,Bs,acc);
                store_out(acc, out+(size_t)mt*64*(T*V)+(size_t)(t-1)*V+nt*64, T*V, bout+nt*64);
            }
        } else if(cta>=64){
            const int cc=cta-64, mt=cc>>5, nt=cc&31;
            gcore4(h1p+(size_t)mt*64*H, H, g_wD1hh+(size_t)nt*64*H, H, H, As,Bs,accW);
        }
        gbar(ph);

        // ---- P2: attention (CTA = batch), bf16 enc
        {
            const int b=cta;
            for(int k=tid*4;k<H2;k+=NT*4)
                *(float4*)&qs[k]=__ldcg((const float4*)(g_q+(size_t)b*H2+k));
            __syncthreads();
            for(int s=w;s<S;s+=8){
                const __nv_bfloat16* eb=enc+((size_t)s*B+b)*H2;
                float sum=0.f;
                #pragma unroll
                for(int k=lane*8;k<H2;k+=256){
                    const uint4 ev=*(const uint4*)(eb+k);
                    const float2 f0=bf2f(ev.x), f1=bf2f(ev.y);
                    const float2 f2=bf2f(ev.z), f3=bf2f(ev.w);
                    sum+=f0.x*qs[k]+f0.y*qs[k+1]+f1.x*qs[k+2]+f1.y*qs[k+3]
                        +f2.x*qs[k+4]+f2.y*qs[k+5]+f3.x*qs[k+6]+f3.y*qs[k+7];
                }
                #pragma unroll
                for(int o=16;o;o>>=1) sum+=__shfl_xor_sync(0xffffffffu,sum,o);
                if(lane==0) sc[s]=(src[b*S+s]!=0)?sum:-1e9f;
            }
            __syncthreads();
            const float v=sc[tid];
            float m=v;
            #pragma unroll
            for(int o=16;o;o>>=1) m=fmaxf(m,__shfl_xor_sync(0xffffffffu,m,o));
            if(lane==0) red[w]=m;
            __syncthreads();
            if(tid==0){
                float mm=red[0];
                #pragma unroll
                for(int i=1;i<8;++i) mm=fmaxf(mm,red[i]);
                s_max=mm;
            }
            __syncthreads();
            const float ev=expf(v-s_max);
            float sum=ev;
            #pragma unroll
            for(int o=16;o;o>>=1) sum+=__shfl_xor_sync(0xffffffffu,sum,o);
            if(lane==0) red[w]=sum;
            __syncthreads();
            if(tid==0){
                float ss=0.f;
                #pragma unroll
                for(int i=0;i<8;++i) ss+=red[i];
                s_sum=ss;
            }
            __syncthreads();
            sc[tid]=ev/s_sum;
            __syncthreads();
            const int k4=tid*4;
            float4 a={0.f,0.f,0.f,0.f};
            const __nv_bfloat16* ep=enc+(size_t)b*H2+k4;
            #pragma unroll 8
            for(int s=0;s<S;++s){
                const float p=sc[s];
                const uint2 ev2=*(const uint2*)(ep+(size_t)s*B*H2);
                const float2 f0=bf2f(ev2.x), f1=bf2f(ev2.y);
                a.x+=p*f0.x; a.y+=p*f0.y; a.z+=p*f1.x; a.w+=p*f1.y;
            }
            *(float4*)(g_ctx+(size_t)b*H2+k4)=a;
        }
        gbar(ph);

        // ---- P3: cell0 K-split. Owner (0..63): ctx[0:768]*Wc, regs.
        //      Partner (64..127): ctx[768:1024]*Wc + d0h_prev*whh0 -> g_gates.
        ull acc[4][2]={{0,0},{0,0},{0,0},{0,0}};
        if(cta<64){
            const int mt=cta>>5, nt=cta&31;
            gcore4(g_ctx+(size_t)mt*64*H2, H2, g_wD0+E+(size_t)nt*64*EH2, EH2, 768, As,Bs,acc);
        } else {
            const int cc=cta-64, mt=cc>>5, nt=cc&31;
            gcore4(g_ctx+(size_t)mt*64*H2+768, H2, g_wD0+E+768+(size_t)nt*64*EH2, EH2, 256, As,Bs,acc);
            gcore4(g_d0hb[par^1]+(size_t)mt*64*H, H, g_wD0hh+(size_t)nt*64*H, H, H, As,Bs,acc);
            store_raw(acc, g_gates+(size_t)(mt*64)*G+nt*64, G);
        }
        gbar(ph);

        // ---- P4: cell0 epilogue (owner combines reg acc + partner partial + pre)
        if(cta<64){
            const int mt=cta>>5, nt=cta&31;
            const float* preT=pre+((size_t)t*B+mt*64)*G+nt*64;
            const float* parT=g_gates+(size_t)(mt*64)*G+nt*64;
            float* hout=g_d0hb[par];
            #pragma unroll
            for(int r=0;r<4;++r){
                const int row=ty*4+r;
                const int b=mt*64+row;
                const float4 pv=__ldcg((const float4*)(preT+(size_t)row*G+tx*4));
                const float4 gv=__ldcg((const float4*)(parT+(size_t)row*G+tx*4));
                const float gi=accf(acc[r][0],0)+pv.x+gv.x;
                const float gf=accf(acc[r][0],1)+pv.y+gv.y;
                const float gg=accf(acc[r][1],0)+pv.z+gv.z;
                const float go=accf(acc[r][1],1)+pv.w+gv.w;
                const float cn=sigf(gf)*c[r]+sigf(gi)*tanhf(gg);
                c[r]=cn;
                hout[(size_t)b*H+nt*16+tx]=sigf(go)*tanhf(cn);
            }
        }
        gbar(ph);

        // ---- P5: cell1 (owner 64..127): wih1*d0h_t into accW, fused epilogue
        if(cta>=64){
            const int cc=cta-64, mt=cc>>5, nt=cc&31;
            gcore4(g_d0hb[par]+(size_t)mt*64*H, H, g_wD1ih+(size_t)nt*64*H, H, H, As,Bs,accW);
            float* hout=g_d1hb[par];
            const float4 bv=*(const float4*)(g_bd1+nt*64+tx*4);
            #pragma unroll
            for(int r=0;r<4;++r){
                const int b=mt*64+ty*4+r;
                const float gi=accf(accW[r][0],0)+bv.x;
                const float gf=accf(accW[r][0],1)+bv.y;
                const float gg=accf(accW[r][1],0)+bv.z;
                const float go=accf(accW[r][1],1)+bv.w;
                const float cn=sigf(gf)*c[r]+sigf(gi)*tanhf(gg);
                c[r]=cn;
                hout[(size_t)b*H+nt*16+tx]=sigf(go)*tanhf(cn);
            }
        }
        gbar(ph);
    }
    // final logits (t = T-1); last d1h written to parity (T-1)&1 = 1
    if(cta>=32&&cta<48){
        const int ct=cta-32, mt=ct>>3, nt=ct&7;
        ull acc[4][2]={{0,0},{0,0},{0,0},{0,0}};
        gcore4(g_d1hb[1]+(size_t)mt*64*H, H, Wout+(size_t)nt*64*H, H, H, As,Bs,acc);
        store_out(acc, out+(size_t)mt*64*(T*V)+(size_t)(T-1)*V+nt*64, T*V, bout+nt*64);
    }
}

// ---------------- host ----------------
static inline void* sym(const void* s){ void* p=nullptr; cudaGetSymbolAddress(&p,s); return p; }

extern "C" void kernel_launch(void* const* d_in, const int* in_sizes, int n_in,
                              void* d_out, int out_size)
{
    (void)in_sizes;(void)n_in;(void)out_size;
    const int* src=(const int*)d_in[0];
    const int* decin=(const int*)d_in[1];
    const float* emb=(const float*)d_in[2];
    const float* eWih0=(const float*)d_in[3];
    const float* eWhh0=(const float*)d_in[4];
    const float* ebih0=(const float*)d_in[5];
    const float* ebhh0=(const float*)d_in[6];
    const float* eWih1=(const float*)d_in[7];
    const float* eWhh1=(const float*)d_in[8];
    const float* ebih1=(const float*)d_in[9];
    const float* ebhh1=(const float*)d_in[10];
    const float* dWih0=(const float*)d_in[11];
    const float* dWhh0=(const float*)d_in[12];
    const float* dbih0=(const float*)d_in[13];
    const float* dbhh0=(const float*)d_in[14];
    const float* dWih1=(const float*)d_in[15];
    const float* dWhh1=(const float*)d_in[16];
    const float* dbih1=(const float*)d_in[17];
    const float* dbhh1=(const float*)d_in[18];
    const float* Wq=(const float*)d_in[19];
    const float* bq=(const float*)d_in[20];
    const float* Wout=(const float*)d_in[21];
    const float* bout=(const float*)d_in[22];
    float* out=(float*)d_out;

    float* xs=(float*)sym(g_xs);    float* pre=(float*)sym(g_pre);
    float* preD=(float*)sym(g_preD);
    float* y0=(float*)sym(g_y0);
    __nv_bfloat16* encb=(__nv_bfloat16*)sym(g_encb);
    float* edec=(float*)sym(g_edec);
    float* wE0ih=(float*)sym(g_wE0ih); float* wE0hh=(float*)sym(g_wE0hh);
    float* wE1ih=(float*)sym(g_wE1ih); float* wE1hh=(float*)sym(g_wE1hh);
    float* wD0=(float*)sym(g_wD0);
    float* be0=(float*)sym(g_be0);  float* be1=(float*)sym(g_be1);
    float* bd0=(float*)sym(g_bd0);
    float* h0i=(float*)sym(g_h0i);  float* c0i=(float*)sym(g_c0i);
    float* h1i=(float*)sym(g_h1i);  float* c1i=(float*)sym(g_c1i);

    prep_k<<<512,NT>>>(src,decin,emb,
        eWih0,eWhh0,ebih0,ebhh0, eWih1,eWhh1,ebih1,ebhh1,
        dWih0,dWhh0,dbih0,dbhh0, dWih1,dWhh1,dbih1,dbhh1);

    const long long SBG=(long long)S*B*G;
    // decoder embedding projection (into separate preD; launched early so ncu
    // -s 5 lands on enc_layer_k)
    gemm2_k<<<dim3(32,(T*B)/64,1),256>>>(edec,E,E, wD0,EH2, bd0, preD,G, 0,0,0,0);
    // encoder layer0 input projections
    gemm2_k<<<dim3(32,(S*B)/64,2),256>>>(xs,E,E, wE0ih,E, be0, pre,G,
        (long long)S*B*E,(long long)G*E,G,SBG);
    enc_layer_k<<<NB,NT>>>(pre, wE0hh, y0, y0+(size_t)S*B*H2, nullptr, h0i,c0i);
    // encoder layer1 input projections
    gemm2_k<<<dim3(32,(S*B)/64,2),256>>>(y0,H2,H2, wE1ih,H2, be1, pre,G,
        (long long)S*B*H2,(long long)G*H2,G,SBG);
    enc_layer_k<<<NB,NT>>>(pre, wE1hh, nullptr, nullptr, encb, h1i,c1i);
    // decoder
    dec_k<<<NB,NT>>>(preD, src, encb, Wq,bq, Wout,bout, out);
}